// round 4
// baseline (speedup 1.0000x reference)
#include <cuda_runtime.h>
#include <cstdint>
#include <cstddef>

// Problem constants
#define B_   2
#define LQ_  2048
#define LKV_ 2048
#define DQ_  1024
#define HID_ 1024
#define NH_  16
#define HD_  64
#define EPS_ 1e-5f

// Scratch (allocation-free rule: __device__ globals)
__device__ float g_Qp[B_ * LQ_ * HID_];
__device__ float g_Kp[B_ * LKV_ * HID_];
__device__ float g_Vp[B_ * LKV_ * HID_];
__device__ float g_Ctx[B_ * LQ_ * HID_];
__device__ float g_X[B_ * LQ_ * DQ_];

// ---------------------------------------------------------------------------
// Helpers
// ---------------------------------------------------------------------------
// D = A(16x8,row) * B(8x8,col) + D ; tf32 in (raw fp32 bits ok), fp32 accum
__device__ __forceinline__ void mma_tf32(float c[4], const uint32_t a[4], const uint32_t b[2]) {
    asm volatile(
        "mma.sync.aligned.m16n8k8.row.col.f32.tf32.tf32.f32 "
        "{%0,%1,%2,%3}, {%4,%5,%6,%7}, {%8,%9}, {%0,%1,%2,%3};\n"
        : "+f"(c[0]), "+f"(c[1]), "+f"(c[2]), "+f"(c[3])
        : "r"(a[0]), "r"(a[1]), "r"(a[2]), "r"(a[3]), "r"(b[0]), "r"(b[1]));
}

__device__ __forceinline__ void cp_async16(uint32_t* smem_dst, const void* gsrc) {
    uint32_t s = (uint32_t)__cvta_generic_to_shared(smem_dst);
    asm volatile("cp.async.cg.shared.global [%0], [%1], 16;\n" :: "r"(s), "l"(gsrc));
}
__device__ __forceinline__ void cp_commit() {
    asm volatile("cp.async.commit_group;\n");
}
template <int N>
__device__ __forceinline__ void cp_wait() {
    asm volatile("cp.async.wait_group %0;\n" :: "n"(N));
}

// FMA-only 2^x (no MUFU). |err| ~ 2e-6 rel. Valid for x <= ~120.
__device__ __forceinline__ float exp2_fast(float x) {
    x = fmaxf(x, -120.f);
    float t = x + 12582912.f;                       // 1.5 * 2^23 magic
    int n = __float_as_int(t) - 0x4B400000;
    float f = x - (t - 12582912.f);
    float p = 1.33335581e-3f;
    p = fmaf(p, f, 9.61812910e-3f);
    p = fmaf(p, f, 5.55041087e-2f);
    p = fmaf(p, f, 2.40226507e-1f);
    p = fmaf(p, f, 6.93147182e-1f);
    p = fmaf(p, f, 1.0f);
    return __int_as_float(__float_as_int(p) + (n << 23));
}

// ---------------------------------------------------------------------------
// TF32 GEMM: C[M,N] = A[M,K] @ W[K,N] + bias (+ residual)
// Block tile 128x128, BK=32, 256 threads (8 warps, 2x4), warp tile 64x32.
// cp.async 2-stage double buffer, raw fp32 fed as tf32.
// ---------------------------------------------------------------------------
#define GBM 128
#define GBN 128
#define GBK 32
#define AS_LD 36
#define BS_LD 132
#define A_STG (GBM * AS_LD)
#define B_STG (GBK * BS_LD)
#define GEMM_SMEM ((2 * A_STG + 2 * B_STG) * 4)

__global__ __launch_bounds__(256) void gemm_tf32_kernel(
    const float* __restrict__ A, const float* __restrict__ W,
    const float* __restrict__ bias, const float* __restrict__ residual,
    float* __restrict__ C, int M, int N, int K)
{
    extern __shared__ uint32_t gsm[];
    uint32_t* AsB = gsm;                 // [2][A_STG]
    uint32_t* BsB = gsm + 2 * A_STG;     // [2][B_STG]

    const int tid  = threadIdx.x;
    const int lane = tid & 31;
    const int warp = tid >> 5;
    const int warpRow = (warp >> 2) * 64;
    const int warpCol = (warp & 3) * 32;
    const int row0 = blockIdx.y * GBM;
    const int col0 = blockIdx.x * GBN;

    float cf[4][4][4];
    #pragma unroll
    for (int mt = 0; mt < 4; mt++)
        #pragma unroll
        for (int nt = 0; nt < 4; nt++)
            #pragma unroll
            for (int i = 0; i < 4; i++) cf[mt][nt][i] = 0.f;

    const int nT = K / GBK;

    // stage fill via cp.async
    auto fill = [&](int s, int k0) {
        uint32_t* As = AsB + s * A_STG;
        uint32_t* Bs = BsB + s * B_STG;
        #pragma unroll
        for (int i = 0; i < 4; i++) {
            int q = tid + 256 * i;
            int r = q >> 3, c = (q & 7) * 4;
            cp_async16(&As[r * AS_LD + c], &A[(size_t)(row0 + r) * K + k0 + c]);
        }
        #pragma unroll
        for (int i = 0; i < 4; i++) {
            int q = tid + 256 * i;
            int r = q >> 5, c = (q & 31) * 4;
            cp_async16(&Bs[r * BS_LD + c], &W[(size_t)(k0 + r) * N + col0 + c]);
        }
    };

    fill(0, 0);
    cp_commit();

    for (int t = 0; t < nT; t++) {
        if (t + 1 < nT) fill((t + 1) & 1, (t + 1) * GBK);
        cp_commit();
        cp_wait<1>();
        __syncthreads();

        const uint32_t* As = AsB + (t & 1) * A_STG;
        const uint32_t* Bs = BsB + (t & 1) * B_STG;

        #pragma unroll
        for (int ks = 0; ks < 4; ks++) {
            uint32_t af[4][4], bf[4][2];
            #pragma unroll
            for (int mt = 0; mt < 4; mt++) {
                int r = warpRow + 16 * mt + (lane >> 2);
                int c = 8 * ks + (lane & 3);
                af[mt][0] = As[r * AS_LD + c];
                af[mt][1] = As[(r + 8) * AS_LD + c];
                af[mt][2] = As[r * AS_LD + c + 4];
                af[mt][3] = As[(r + 8) * AS_LD + c + 4];
            }
            #pragma unroll
            for (int nt = 0; nt < 4; nt++) {
                int c = warpCol + 8 * nt + (lane >> 2);
                int r = 8 * ks + (lane & 3);
                bf[nt][0] = Bs[r * BS_LD + c];
                bf[nt][1] = Bs[(r + 4) * BS_LD + c];
            }
            #pragma unroll
            for (int mt = 0; mt < 4; mt++)
                #pragma unroll
                for (int nt = 0; nt < 4; nt++)
                    mma_tf32(cf[mt][nt], af[mt], bf[nt]);
        }
        __syncthreads();
    }

    // Epilogue: bias (+residual), float2 stores
    #pragma unroll
    for (int mt = 0; mt < 4; mt++) {
        int r  = row0 + warpRow + 16 * mt + (lane >> 2);
        int r2 = r + 8;
        #pragma unroll
        for (int nt = 0; nt < 4; nt++) {
            int c = col0 + warpCol + 8 * nt + 2 * (lane & 3);
            float b0 = bias[c], b1 = bias[c + 1];
            float v0 = cf[mt][nt][0] + b0, v1 = cf[mt][nt][1] + b1;
            float v2 = cf[mt][nt][2] + b0, v3 = cf[mt][nt][3] + b1;
            if (residual) {
                v0 += residual[(size_t)r  * N + c];
                v1 += residual[(size_t)r  * N + c + 1];
                v2 += residual[(size_t)r2 * N + c];
                v3 += residual[(size_t)r2 * N + c + 1];
            }
            *(float2*)&C[(size_t)r  * N + c] = make_float2(v0, v1);
            *(float2*)&C[(size_t)r2 * N + c] = make_float2(v2, v3);
        }
    }
}

// ---------------------------------------------------------------------------
// Flash attention, tensor cores (tf32 raw-bits), cp.async double-buffered K/V.
// 256 threads (8 warps), block = 128 queries of one (b,h); warp owns 16 rows.
// KV tile = 64. P kept per-warp in smem with row-paired layout (64-bit ops).
// ---------------------------------------------------------------------------
#define KS_LD 68
#define VS_LD 72
#define P_LDR 136                       // words per r0-row (rows r, r+8 interleaved)
#define K_STG (64 * KS_LD)
#define V_STG (64 * VS_LD)
#define P_WARP (8 * P_LDR)
#define ATT_SMEM ((2 * K_STG + 2 * V_STG + 8 * P_WARP) * 4)

__global__ __launch_bounds__(256) void attention_tc_kernel(
    const float* __restrict__ Qp, const float* __restrict__ Kp,
    const float* __restrict__ Vp, float* __restrict__ Ctx)
{
    extern __shared__ uint32_t asm_[];
    uint32_t* KsB = asm_;                          // [2][K_STG]
    uint32_t* VsB = asm_ + 2 * K_STG;              // [2][V_STG]
    uint32_t* Ps  = asm_ + 2 * K_STG + 2 * V_STG;  // [8][P_WARP]

    const int tid  = threadIdx.x;
    const int lane = tid & 31;
    const int warp = tid >> 5;
    const int r0   = lane >> 2;
    const int qd   = lane & 3;
    const int b  = blockIdx.z;
    const int h  = blockIdx.y;
    const int q0 = blockIdx.x * 128;
    const int lr = warp * 16 + r0;                 // this thread's query row (and +8)
    const float SC = 0.125f * 1.44269504089f;      // 1/sqrt(64) * log2(e)

    uint32_t* Pw = Ps + warp * P_WARP;

    // Q fragments straight from GMEM (scaled; raw bits as tf32)
    uint32_t qf[8][4];
    {
        const float* q0p = Qp + ((size_t)(b * LQ_ + q0 + lr) * HID_ + h * HD_);
        const float* q1p = q0p + (size_t)8 * HID_;
        #pragma unroll
        for (int ks = 0; ks < 8; ks++) {
            int c = 8 * ks + qd;
            qf[ks][0] = __float_as_uint(q0p[c] * SC);
            qf[ks][1] = __float_as_uint(q1p[c] * SC);
            qf[ks][2] = __float_as_uint(q0p[c + 4] * SC);
            qf[ks][3] = __float_as_uint(q1p[c + 4] * SC);
        }
    }

    float of[8][4];
    #pragma unroll
    for (int nt = 0; nt < 8; nt++)
        #pragma unroll
        for (int i = 0; i < 4; i++) of[nt][i] = 0.f;
    float m0 = -1e30f, m1 = -1e30f, l0 = 0.f, l1 = 0.f;

    const float* Kbase = Kp + ((size_t)b * LKV_ * HID_ + h * HD_);
    const float* Vbase = Vp + ((size_t)b * LKV_ * HID_ + h * HD_);

    auto fill = [&](int s, int kt) {
        uint32_t* Ks = KsB + s * K_STG;
        uint32_t* Vs = VsB + s * V_STG;
        #pragma unroll
        for (int i = 0; i < 4; i++) {
            int q = tid + 256 * i;
            int r = q >> 4, c = (q & 15) * 4;
            const float* src = Kbase + (size_t)(kt + r) * HID_ + c;
            cp_async16(&Ks[r * KS_LD + c], src);
        }
        #pragma unroll
        for (int i = 0; i < 4; i++) {
            int q = tid + 256 * i;
            int r = q >> 4, c = (q & 15) * 4;
            const float* src = Vbase + (size_t)(kt + r) * HID_ + c;
            cp_async16(&Vs[r * VS_LD + c], src);
        }
    };

    fill(0, 0);
    cp_commit();

    const int nT = LKV_ / 64;
    for (int t = 0; t < nT; t++) {
        if (t + 1 < nT) fill((t + 1) & 1, (t + 1) * 64);
        cp_commit();
        cp_wait<1>();
        __syncthreads();

        const uint32_t* Ks = KsB + (t & 1) * K_STG;
        const uint32_t* Vs = VsB + (t & 1) * V_STG;

        // S = Q @ K^T
        float sf[8][4];
        #pragma unroll
        for (int nt = 0; nt < 8; nt++)
            #pragma unroll
            for (int i = 0; i < 4; i++) sf[nt][i] = 0.f;
        #pragma unroll
        for (int ks = 0; ks < 8; ks++) {
            #pragma unroll
            for (int nt = 0; nt < 8; nt++) {
                uint32_t bfr[2];
                int keyrow = 8 * nt + r0;
                int dcol = 8 * ks + qd;
                bfr[0] = Ks[keyrow * KS_LD + dcol];
                bfr[1] = Ks[keyrow * KS_LD + dcol + 4];
                mma_tf32(sf[nt], qf[ks], bfr);
            }
        }

        // Online softmax (exp2 domain)
        float mloc0 = -1e30f, mloc1 = -1e30f;
        #pragma unroll
        for (int nt = 0; nt < 8; nt++) {
            mloc0 = fmaxf(mloc0, fmaxf(sf[nt][0], sf[nt][1]));
            mloc1 = fmaxf(mloc1, fmaxf(sf[nt][2], sf[nt][3]));
        }
        mloc0 = fmaxf(mloc0, __shfl_xor_sync(0xffffffff, mloc0, 1));
        mloc0 = fmaxf(mloc0, __shfl_xor_sync(0xffffffff, mloc0, 2));
        mloc1 = fmaxf(mloc1, __shfl_xor_sync(0xffffffff, mloc1, 1));
        mloc1 = fmaxf(mloc1, __shfl_xor_sync(0xffffffff, mloc1, 2));

        float mn0 = fmaxf(m0, mloc0), mn1 = fmaxf(m1, mloc1);
        float corr0 = exp2_fast(m0 - mn0), corr1 = exp2_fast(m1 - mn1);
        m0 = mn0; m1 = mn1;

        float rs0 = 0.f, rs1 = 0.f;
        #pragma unroll
        for (int nt = 0; nt < 8; nt++) {
            float p0 = exp2_fast(sf[nt][0] - mn0);
            float p1 = exp2_fast(sf[nt][1] - mn0);
            float p2 = exp2_fast(sf[nt][2] - mn1);
            float p3 = exp2_fast(sf[nt][3] - mn1);
            rs0 += p0 + p1;
            rs1 += p2 + p3;
            int c = 8 * nt + 2 * qd;
            // row-paired P: word addr = r0*P_LDR + 2*col + hi(row)
            uint2 w0; w0.x = __float_as_uint(p0); w0.y = __float_as_uint(p2);
            uint2 w1; w1.x = __float_as_uint(p1); w1.y = __float_as_uint(p3);
            *(uint2*)&Pw[r0 * P_LDR + 2 * c]     = w0;
            *(uint2*)&Pw[r0 * P_LDR + 2 * c + 2] = w1;
        }
        rs0 += __shfl_xor_sync(0xffffffff, rs0, 1);
        rs0 += __shfl_xor_sync(0xffffffff, rs0, 2);
        rs1 += __shfl_xor_sync(0xffffffff, rs1, 1);
        rs1 += __shfl_xor_sync(0xffffffff, rs1, 2);
        l0 = l0 * corr0 + rs0;
        l1 = l1 * corr1 + rs1;

        #pragma unroll
        for (int nt = 0; nt < 8; nt++) {
            of[nt][0] *= corr0; of[nt][1] *= corr0;
            of[nt][2] *= corr1; of[nt][3] *= corr1;
        }
        __syncwarp();

        // O += P @ V
        #pragma unroll
        for (int ks = 0; ks < 8; ks++) {
            uint32_t af[4];
            int c = 8 * ks + qd;
            uint2 u = *(const uint2*)&Pw[r0 * P_LDR + 2 * c];
            uint2 v = *(const uint2*)&Pw[r0 * P_LDR + 2 * c + 8];
            af[0] = u.x; af[1] = u.y; af[2] = v.x; af[3] = v.y;
            #pragma unroll
            for (int nt = 0; nt < 8; nt++) {
                uint32_t bfr[2];
                int kr = 8 * ks + qd;
                int dc = 8 * nt + r0;
                bfr[0] = Vs[kr * VS_LD + dc];
                bfr[1] = Vs[(kr + 4) * VS_LD + dc];
                mma_tf32(of[nt], af, bfr);
            }
        }
        __syncthreads();
    }

    // Normalize + store
    float inv0 = 1.f / l0, inv1 = 1.f / l1;
    float* o0p = Ctx + ((size_t)(b * LQ_ + q0 + lr) * HID_ + h * HD_);
    float* o1p = o0p + (size_t)8 * HID_;
    #pragma unroll
    for (int nt = 0; nt < 8; nt++) {
        int c = 8 * nt + 2 * qd;
        *(float2*)&o0p[c] = make_float2(of[nt][0] * inv0, of[nt][1] * inv0);
        *(float2*)&o1p[c] = make_float2(of[nt][2] * inv1, of[nt][3] * inv1);
    }
}

// ---------------------------------------------------------------------------
// LayerNorm over rows of 1024. One block (256 threads) per row.
// ---------------------------------------------------------------------------
__global__ __launch_bounds__(256) void layernorm_kernel(
    const float* __restrict__ X, const float* __restrict__ gamma,
    const float* __restrict__ beta, float* __restrict__ out)
{
    __shared__ float red_s[8];
    __shared__ float red_ss[8];

    const int row = blockIdx.x;
    const int tid = threadIdx.x;
    const float* x = X + (size_t)row * DQ_;

    float s = 0.f, ss = 0.f;
    #pragma unroll
    for (int i = tid; i < DQ_; i += 256) {
        float v = x[i];
        s += v;
        ss += v * v;
    }
    #pragma unroll
    for (int off = 16; off > 0; off >>= 1) {
        s  += __shfl_xor_sync(0xffffffff, s, off);
        ss += __shfl_xor_sync(0xffffffff, ss, off);
    }
    if ((tid & 31) == 0) {
        red_s[tid >> 5] = s;
        red_ss[tid >> 5] = ss;
    }
    __syncthreads();
    if (tid < 32) {
        float a = (tid < 8) ? red_s[tid] : 0.f;
        float c = (tid < 8) ? red_ss[tid] : 0.f;
        #pragma unroll
        for (int off = 4; off > 0; off >>= 1) {
            a += __shfl_xor_sync(0xffffffff, a, off);
            c += __shfl_xor_sync(0xffffffff, c, off);
        }
        if (tid == 0) { red_s[0] = a; red_ss[0] = c; }
    }
    __syncthreads();

    const float mu = red_s[0] * (1.f / DQ_);
    const float var = red_ss[0] * (1.f / DQ_) - mu * mu;
    const float rstd = rsqrtf(var + EPS_);

    float* orow = out + (size_t)row * DQ_;
    for (int i = tid; i < DQ_; i += 256) {
        orow[i] = (x[i] - mu) * rstd * gamma[i] + beta[i];
    }
}

// ---------------------------------------------------------------------------
// Launch
// ---------------------------------------------------------------------------
extern "C" void kernel_launch(void* const* d_in, const int* in_sizes, int n_in,
                              void* d_out, int out_size)
{
    const float* query     = (const float*)d_in[0];
    const float* key_value = (const float*)d_in[1];
    const float* Wq = (const float*)d_in[2];
    const float* bq = (const float*)d_in[3];
    const float* Wk = (const float*)d_in[4];
    const float* bk = (const float*)d_in[5];
    const float* Wv = (const float*)d_in[6];
    const float* bv = (const float*)d_in[7];
    const float* Wo = (const float*)d_in[8];
    const float* bo = (const float*)d_in[9];
    const float* ln_gamma = (const float*)d_in[10];
    const float* ln_beta  = (const float*)d_in[11];
    float* out = (float*)d_out;

    float *Qp, *Kp, *Vp, *Ctx, *X;
    cudaGetSymbolAddress((void**)&Qp, g_Qp);
    cudaGetSymbolAddress((void**)&Kp, g_Kp);
    cudaGetSymbolAddress((void**)&Vp, g_Vp);
    cudaGetSymbolAddress((void**)&Ctx, g_Ctx);
    cudaGetSymbolAddress((void**)&X, g_X);

    const int M = B_ * LQ_;   // 4096
    const int K = DQ_;        // 1024
    const int N = HID_;       // 1024

    // Not stream ops — safe under graph capture; no static guards allowed.
    cudaFuncSetAttribute(gemm_tf32_kernel,
                         cudaFuncAttributeMaxDynamicSharedMemorySize, GEMM_SMEM);
    cudaFuncSetAttribute(attention_tc_kernel,
                         cudaFuncAttributeMaxDynamicSharedMemorySize, ATT_SMEM);

    dim3 ggrid(N / GBN, M / GBM);

    gemm_tf32_kernel<<<ggrid, 256, GEMM_SMEM>>>(query,     Wq, bq, nullptr, Qp, M, N, K);
    gemm_tf32_kernel<<<ggrid, 256, GEMM_SMEM>>>(key_value, Wk, bk, nullptr, Kp, M, N, K);
    gemm_tf32_kernel<<<ggrid, 256, GEMM_SMEM>>>(key_value, Wv, bv, nullptr, Vp, M, N, K);

    dim3 agrid(LQ_ / 128, NH_, B_);
    attention_tc_kernel<<<agrid, 256, ATT_SMEM>>>(Qp, Kp, Vp, Ctx);

    gemm_tf32_kernel<<<ggrid, 256, GEMM_SMEM>>>(Ctx, Wo, bo, query, X, M, DQ_, HID_);

    layernorm_kernel<<<M, 256>>>(X, ln_gamma, ln_beta, out);
}

// round 5
// speedup vs baseline: 1.5920x; 1.5920x over previous
#include <cuda_runtime.h>
#include <cuda_bf16.h>
#include <cstdint>
#include <cstddef>

// Problem constants
#define B_   2
#define LQ_  2048
#define LKV_ 2048
#define DQ_  1024
#define HID_ 1024
#define NH_  16
#define HD_  64
#define EPS_ 1e-5f

// Scratch (allocation-free rule: __device__ globals)
__device__ __nv_bfloat16 g_Qin[B_ * LQ_ * DQ_];    // bf16(query)
__device__ __nv_bfloat16 g_KVin[B_ * LKV_ * DQ_];  // bf16(key_value)
__device__ __nv_bfloat16 g_Wqt[HID_ * DQ_];        // Wq^T bf16 [n][k]
__device__ __nv_bfloat16 g_Wkt[HID_ * DQ_];
__device__ __nv_bfloat16 g_Wvt[HID_ * DQ_];
__device__ __nv_bfloat16 g_Wot[DQ_ * HID_];
__device__ __nv_bfloat16 g_Qp[B_ * LQ_ * HID_];
__device__ __nv_bfloat16 g_Kp[B_ * LKV_ * HID_];
__device__ __nv_bfloat16 g_Vp[B_ * LKV_ * HID_];
__device__ __nv_bfloat16 g_Vt[B_ * NH_ * HD_ * LKV_];  // [b][h][d][key]
__device__ __nv_bfloat16 g_Ctx[B_ * LQ_ * HID_];
__device__ float g_X[B_ * LQ_ * DQ_];

// ---------------------------------------------------------------------------
// Helpers
// ---------------------------------------------------------------------------
// D(16x8,f32) += A(16x16,row,bf16) * B(16x8,col,bf16)
__device__ __forceinline__ void mma_bf16(float c[4], const uint32_t a[4], const uint32_t b[2]) {
    asm volatile(
        "mma.sync.aligned.m16n8k16.row.col.f32.bf16.bf16.f32 "
        "{%0,%1,%2,%3}, {%4,%5,%6,%7}, {%8,%9}, {%0,%1,%2,%3};\n"
        : "+f"(c[0]), "+f"(c[1]), "+f"(c[2]), "+f"(c[3])
        : "r"(a[0]), "r"(a[1]), "r"(a[2]), "r"(a[3]), "r"(b[0]), "r"(b[1]));
}

__device__ __forceinline__ uint32_t pack_bf16(float lo, float hi) {
    __nv_bfloat162 p = __floats2bfloat162_rn(lo, hi);
    return *(uint32_t*)&p;
}

__device__ __forceinline__ void cp_async16(void* smem_dst, const void* gsrc) {
    uint32_t s = (uint32_t)__cvta_generic_to_shared(smem_dst);
    asm volatile("cp.async.cg.shared.global [%0], [%1], 16;\n" :: "r"(s), "l"(gsrc));
}
__device__ __forceinline__ void cp_commit() {
    asm volatile("cp.async.commit_group;\n");
}
template <int N>
__device__ __forceinline__ void cp_wait() {
    asm volatile("cp.async.wait_group %0;\n" :: "n"(N));
}

// FMA-only 2^x (no MUFU). |err| ~ 2e-6 rel.
__device__ __forceinline__ float exp2_fast(float x) {
    x = fmaxf(x, -120.f);
    float t = x + 12582912.f;
    int n = __float_as_int(t) - 0x4B400000;
    float f = x - (t - 12582912.f);
    float p = 1.33335581e-3f;
    p = fmaf(p, f, 9.61812910e-3f);
    p = fmaf(p, f, 5.55041087e-2f);
    p = fmaf(p, f, 2.40226507e-1f);
    p = fmaf(p, f, 6.93147182e-1f);
    p = fmaf(p, f, 1.0f);
    return __int_as_float(__float_as_int(p) + (n << 23));
}

// ---------------------------------------------------------------------------
// Conversion kernels
// ---------------------------------------------------------------------------
__global__ __launch_bounds__(256) void cvt_bf16_kernel(
    const float* __restrict__ in, __nv_bfloat16* __restrict__ out, int n4)
{
    int t = blockIdx.x * 256 + threadIdx.x;
    if (t < n4) {
        float4 v = *(const float4*)&in[4 * t];
        uint2 o;
        o.x = pack_bf16(v.x, v.y);
        o.y = pack_bf16(v.z, v.w);
        *(uint2*)&out[4 * t] = o;
    }
}

// W[K][N] f32 -> Wt[N][K] bf16  (K = N = 1024)
__global__ __launch_bounds__(256) void cvt_transpose_w_kernel(
    const float* __restrict__ W, __nv_bfloat16* __restrict__ Wt)
{
    __shared__ float tile[32][33];
    const int tx = threadIdx.x & 31;
    const int ty = threadIdx.x >> 5;   // 0..7
    const int k0 = blockIdx.y * 32;
    const int n0 = blockIdx.x * 32;
    #pragma unroll
    for (int i = 0; i < 4; i++)
        tile[ty + 8 * i][tx] = W[(size_t)(k0 + ty + 8 * i) * 1024 + n0 + tx];
    __syncthreads();
    #pragma unroll
    for (int i = 0; i < 4; i++)
        Wt[(size_t)(n0 + ty + 8 * i) * 1024 + k0 + tx] =
            __float2bfloat16(tile[tx][ty + 8 * i]);
}

// Vp [b][key][h*64+d] bf16 -> Vt [b][h][d][key] bf16
__global__ __launch_bounds__(256) void transpose_v_kernel(
    const __nv_bfloat16* __restrict__ Vp, __nv_bfloat16* __restrict__ Vt)
{
    __shared__ __nv_bfloat16 tile[64][65];
    const int tid = threadIdx.x;
    const int b = blockIdx.z, h = blockIdx.y;
    const int kt = blockIdx.x * 64;
    // load 64 keys x 64 d (scalar smem stores; coalesced gmem reads)
    #pragma unroll
    for (int i = 0; i < 2; i++) {
        int q = tid + 256 * i;
        int r = q >> 3, c = (q & 7) * 8;
        uint4 v = *(const uint4*)&Vp[(size_t)(b * LKV_ + kt + r) * HID_ + h * HD_ + c];
        const __nv_bfloat16* e = (const __nv_bfloat16*)&v;
        #pragma unroll
        for (int j = 0; j < 8; j++) tile[r][c + j] = e[j];
    }
    __syncthreads();
    #pragma unroll
    for (int i = 0; i < 2; i++) {
        int q = tid + 256 * i;
        int d = q >> 3, c = (q & 7) * 8;
        __nv_bfloat16 e[8];
        #pragma unroll
        for (int j = 0; j < 8; j++) e[j] = tile[c + j][d];
        *(uint4*)&Vt[(size_t)((b * NH_ + h) * HD_ + d) * LKV_ + kt + c] = *(uint4*)e;
    }
}

// ---------------------------------------------------------------------------
// BF16 GEMM: C[M,N] = A[M,K] @ Wt[N,K]^T + bias (+ residual)
// Block 128x128, BK=32, 256 threads (8 warps 2x4), warp tile 64x32.
// cp.async double buffer. Output bf16 (proj) or fp32 (+residual).
// ---------------------------------------------------------------------------
#define GBM 128
#define GBN 128
#define GBK 32
#define GLD 40                          // bf16 units per smem row
#define TILE_STG (128 * GLD)            // bf16 elems per A or B stage
#define GEMM_SMEM (4 * TILE_STG * 2)    // 2 stages x (A+B), bytes

__global__ __launch_bounds__(256) void gemm_bf16_kernel(
    const __nv_bfloat16* __restrict__ A, const __nv_bfloat16* __restrict__ Wt,
    const float* __restrict__ bias, const float* __restrict__ residual,
    __nv_bfloat16* __restrict__ Cb, float* __restrict__ Cf,
    int M, int N, int K)
{
    extern __shared__ __nv_bfloat16 gsm[];
    __nv_bfloat16* AsB = gsm;                    // [2][TILE_STG]
    __nv_bfloat16* BsB = gsm + 2 * TILE_STG;     // [2][TILE_STG]

    const int tid  = threadIdx.x;
    const int lane = tid & 31;
    const int warp = tid >> 5;
    const int warpRow = (warp >> 2) * 64;
    const int warpCol = (warp & 3) * 32;
    const int row0 = blockIdx.y * GBM;
    const int col0 = blockIdx.x * GBN;
    const int r0 = lane >> 2, qd = lane & 3;

    float cf[4][4][4];
    #pragma unroll
    for (int mt = 0; mt < 4; mt++)
        #pragma unroll
        for (int nt = 0; nt < 4; nt++)
            #pragma unroll
            for (int i = 0; i < 4; i++) cf[mt][nt][i] = 0.f;

    const int nT = K / GBK;

    auto fill = [&](int s, int k0) {
        __nv_bfloat16* As = AsB + s * TILE_STG;
        __nv_bfloat16* Bs = BsB + s * TILE_STG;
        #pragma unroll
        for (int i = 0; i < 2; i++) {
            int q = tid + 256 * i;
            int r = q >> 2, c = (q & 3) * 8;
            cp_async16(&As[r * GLD + c], &A[(size_t)(row0 + r) * K + k0 + c]);
        }
        #pragma unroll
        for (int i = 0; i < 2; i++) {
            int q = tid + 256 * i;
            int r = q >> 2, c = (q & 3) * 8;
            cp_async16(&Bs[r * GLD + c], &Wt[(size_t)(col0 + r) * K + k0 + c]);
        }
    };

    fill(0, 0);
    cp_commit();

    for (int t = 0; t < nT; t++) {
        if (t + 1 < nT) fill((t + 1) & 1, (t + 1) * GBK);
        cp_commit();
        cp_wait<1>();
        __syncthreads();

        const __nv_bfloat16* As = AsB + (t & 1) * TILE_STG;
        const __nv_bfloat16* Bs = BsB + (t & 1) * TILE_STG;

        #pragma unroll
        for (int ks = 0; ks < 2; ks++) {
            uint32_t af[4][4], bf[4][2];
            #pragma unroll
            for (int mt = 0; mt < 4; mt++) {
                int r = warpRow + 16 * mt + r0;
                int c = 16 * ks + 2 * qd;
                af[mt][0] = *(const uint32_t*)&As[r * GLD + c];
                af[mt][1] = *(const uint32_t*)&As[(r + 8) * GLD + c];
                af[mt][2] = *(const uint32_t*)&As[r * GLD + c + 8];
                af[mt][3] = *(const uint32_t*)&As[(r + 8) * GLD + c + 8];
            }
            #pragma unroll
            for (int nt = 0; nt < 4; nt++) {
                int n = warpCol + 8 * nt + r0;
                int c = 16 * ks + 2 * qd;
                bf[nt][0] = *(const uint32_t*)&Bs[n * GLD + c];
                bf[nt][1] = *(const uint32_t*)&Bs[n * GLD + c + 8];
            }
            #pragma unroll
            for (int mt = 0; mt < 4; mt++)
                #pragma unroll
                for (int nt = 0; nt < 4; nt++)
                    mma_bf16(cf[mt][nt], af[mt], bf[nt]);
        }
        __syncthreads();
    }

    // Epilogue
    #pragma unroll
    for (int mt = 0; mt < 4; mt++) {
        int r  = row0 + warpRow + 16 * mt + r0;
        int r2 = r + 8;
        #pragma unroll
        for (int nt = 0; nt < 4; nt++) {
            int c = col0 + warpCol + 8 * nt + 2 * qd;
            float b0 = bias[c], b1 = bias[c + 1];
            float v0 = cf[mt][nt][0] + b0, v1 = cf[mt][nt][1] + b1;
            float v2 = cf[mt][nt][2] + b0, v3 = cf[mt][nt][3] + b1;
            if (Cb) {
                *(uint32_t*)&Cb[(size_t)r  * N + c] = pack_bf16(v0, v1);
                *(uint32_t*)&Cb[(size_t)r2 * N + c] = pack_bf16(v2, v3);
            } else {
                v0 += residual[(size_t)r  * N + c];
                v1 += residual[(size_t)r  * N + c + 1];
                v2 += residual[(size_t)r2 * N + c];
                v3 += residual[(size_t)r2 * N + c + 1];
                *(float2*)&Cf[(size_t)r  * N + c] = make_float2(v0, v1);
                *(float2*)&Cf[(size_t)r2 * N + c] = make_float2(v2, v3);
            }
        }
    }
}

// ---------------------------------------------------------------------------
// Flash attention, bf16 m16n8k16. 256 threads (8 warps), 128 queries/block.
// KV tile 64. P stays in registers (S C-frag == P A-frag layout).
// V consumed from pre-transposed g_Vt so B-frags have key-adjacent pairs.
// ---------------------------------------------------------------------------
#define KS_LD 72
#define ATT_STG (64 * KS_LD)                 // bf16 elems per K or V stage
#define ATT_SMEM (4 * ATT_STG * 2)           // 2 stages x (K+Vt), bytes

__global__ __launch_bounds__(256) void attention_bf16_kernel(
    const __nv_bfloat16* __restrict__ Qp, const __nv_bfloat16* __restrict__ Kp,
    const __nv_bfloat16* __restrict__ Vt, __nv_bfloat16* __restrict__ Ctx)
{
    extern __shared__ __nv_bfloat16 asmem[];
    __nv_bfloat16* KsB  = asmem;                  // [2][ATT_STG]
    __nv_bfloat16* VtsB = asmem + 2 * ATT_STG;    // [2][ATT_STG]

    const int tid  = threadIdx.x;
    const int lane = tid & 31;
    const int warp = tid >> 5;
    const int r0 = lane >> 2, qd = lane & 3;
    const int b  = blockIdx.z;
    const int h  = blockIdx.y;
    const int q0 = blockIdx.x * 128;
    const int lr = warp * 16 + r0;
    const float SC = 0.125f * 1.44269504089f;     // 1/sqrt(64) * log2(e)

    // Q fragments straight from GMEM bf16 (unscaled; scale applied to scores)
    uint32_t qf[4][4];
    {
        const __nv_bfloat16* q0p = Qp + ((size_t)(b * LQ_ + q0 + lr) * HID_ + h * HD_);
        const __nv_bfloat16* q1p = q0p + (size_t)8 * HID_;
        #pragma unroll
        for (int ks = 0; ks < 4; ks++) {
            int c = 16 * ks + 2 * qd;
            qf[ks][0] = *(const uint32_t*)&q0p[c];
            qf[ks][1] = *(const uint32_t*)&q1p[c];
            qf[ks][2] = *(const uint32_t*)&q0p[c + 8];
            qf[ks][3] = *(const uint32_t*)&q1p[c + 8];
        }
    }

    float of[8][4];
    #pragma unroll
    for (int nt = 0; nt < 8; nt++)
        #pragma unroll
        for (int i = 0; i < 4; i++) of[nt][i] = 0.f;
    float m0 = -1e30f, m1 = -1e30f, l0 = 0.f, l1 = 0.f;

    const __nv_bfloat16* Kbase  = Kp + ((size_t)b * LKV_ * HID_ + h * HD_);
    const __nv_bfloat16* Vtbase = Vt + ((size_t)(b * NH_ + h) * HD_) * LKV_;

    auto fill = [&](int s, int kt) {
        __nv_bfloat16* Ks  = KsB + s * ATT_STG;
        __nv_bfloat16* Vts = VtsB + s * ATT_STG;
        #pragma unroll
        for (int i = 0; i < 2; i++) {
            int q = tid + 256 * i;
            int r = q >> 3, c = (q & 7) * 8;
            cp_async16(&Ks[r * KS_LD + c], &Kbase[(size_t)(kt + r) * HID_ + c]);
        }
        #pragma unroll
        for (int i = 0; i < 2; i++) {
            int q = tid + 256 * i;
            int d = q >> 3, c = (q & 7) * 8;
            cp_async16(&Vts[d * KS_LD + c], &Vtbase[(size_t)d * LKV_ + kt + c]);
        }
    };

    fill(0, 0);
    cp_commit();

    const int nT = LKV_ / 64;
    for (int t = 0; t < nT; t++) {
        if (t + 1 < nT) fill((t + 1) & 1, (t + 1) * 64);
        cp_commit();
        cp_wait<1>();
        __syncthreads();

        const __nv_bfloat16* Ks  = KsB + (t & 1) * ATT_STG;
        const __nv_bfloat16* Vts = VtsB + (t & 1) * ATT_STG;

        // S = Q @ K^T  (raw scores; scale folded into exp)
        float sf[8][4];
        #pragma unroll
        for (int nt = 0; nt < 8; nt++)
            #pragma unroll
            for (int i = 0; i < 4; i++) sf[nt][i] = 0.f;
        #pragma unroll
        for (int ks = 0; ks < 4; ks++) {
            #pragma unroll
            for (int nt = 0; nt < 8; nt++) {
                uint32_t bfr[2];
                int key = 8 * nt + r0;
                int c = 16 * ks + 2 * qd;
                bfr[0] = *(const uint32_t*)&Ks[key * KS_LD + c];
                bfr[1] = *(const uint32_t*)&Ks[key * KS_LD + c + 8];
                mma_bf16(sf[nt], qf[ks], bfr);
            }
        }

        // Online softmax in exp2 domain, scale SC applied here
        float mloc0 = -1e30f, mloc1 = -1e30f;
        #pragma unroll
        for (int nt = 0; nt < 8; nt++) {
            mloc0 = fmaxf(mloc0, fmaxf(sf[nt][0], sf[nt][1]));
            mloc1 = fmaxf(mloc1, fmaxf(sf[nt][2], sf[nt][3]));
        }
        mloc0 = fmaxf(mloc0, __shfl_xor_sync(0xffffffff, mloc0, 1));
        mloc0 = fmaxf(mloc0, __shfl_xor_sync(0xffffffff, mloc0, 2));
        mloc1 = fmaxf(mloc1, __shfl_xor_sync(0xffffffff, mloc1, 1));
        mloc1 = fmaxf(mloc1, __shfl_xor_sync(0xffffffff, mloc1, 2));

        float mn0 = fmaxf(m0, mloc0), mn1 = fmaxf(m1, mloc1);
        float corr0 = exp2_fast((m0 - mn0) * SC);
        float corr1 = exp2_fast((m1 - mn1) * SC);
        m0 = mn0; m1 = mn1;

        float rs0 = 0.f, rs1 = 0.f;
        float pv[8][4];
        #pragma unroll
        for (int nt = 0; nt < 8; nt++) {
            pv[nt][0] = exp2_fast((sf[nt][0] - mn0) * SC);
            pv[nt][1] = exp2_fast((sf[nt][1] - mn0) * SC);
            pv[nt][2] = exp2_fast((sf[nt][2] - mn1) * SC);
            pv[nt][3] = exp2_fast((sf[nt][3] - mn1) * SC);
            rs0 += pv[nt][0] + pv[nt][1];
            rs1 += pv[nt][2] + pv[nt][3];
        }
        rs0 += __shfl_xor_sync(0xffffffff, rs0, 1);
        rs0 += __shfl_xor_sync(0xffffffff, rs0, 2);
        rs1 += __shfl_xor_sync(0xffffffff, rs1, 1);
        rs1 += __shfl_xor_sync(0xffffffff, rs1, 2);
        l0 = l0 * corr0 + rs0;
        l1 = l1 * corr1 + rs1;

        #pragma unroll
        for (int nt = 0; nt < 8; nt++) {
            of[nt][0] *= corr0; of[nt][1] *= corr0;
            of[nt][2] *= corr1; of[nt][3] *= corr1;
        }

        // P A-fragments directly from registers (C-frag layout == A-frag layout)
        uint32_t pf[4][4];
        #pragma unroll
        for (int ks = 0; ks < 4; ks++) {
            pf[ks][0] = pack_bf16(pv[2 * ks][0],     pv[2 * ks][1]);
            pf[ks][1] = pack_bf16(pv[2 * ks][2],     pv[2 * ks][3]);
            pf[ks][2] = pack_bf16(pv[2 * ks + 1][0], pv[2 * ks + 1][1]);
            pf[ks][3] = pack_bf16(pv[2 * ks + 1][2], pv[2 * ks + 1][3]);
        }

        // O += P @ V  (k = keys from Vt: key-adjacent pairs)
        #pragma unroll
        for (int ks = 0; ks < 4; ks++) {
            #pragma unroll
            for (int nt = 0; nt < 8; nt++) {
                uint32_t bfr[2];
                int d = 8 * nt + r0;
                int c = 16 * ks + 2 * qd;
                bfr[0] = *(const uint32_t*)&Vts[d * KS_LD + c];
                bfr[1] = *(const uint32_t*)&Vts[d * KS_LD + c + 8];
                mma_bf16(of[nt], pf[ks], bfr);
            }
        }
        __syncthreads();
    }

    // Normalize + store Ctx (bf16)
    float inv0 = 1.f / l0, inv1 = 1.f / l1;
    __nv_bfloat16* o0p = Ctx + ((size_t)(b * LQ_ + q0 + lr) * HID_ + h * HD_);
    __nv_bfloat16* o1p = o0p + (size_t)8 * HID_;
    #pragma unroll
    for (int nt = 0; nt < 8; nt++) {
        int c = 8 * nt + 2 * qd;
        *(uint32_t*)&o0p[c] = pack_bf16(of[nt][0] * inv0, of[nt][1] * inv0);
        *(uint32_t*)&o1p[c] = pack_bf16(of[nt][2] * inv1, of[nt][3] * inv1);
    }
}

// ---------------------------------------------------------------------------
// LayerNorm over rows of 1024. One block (256 threads) per row.
// ---------------------------------------------------------------------------
__global__ __launch_bounds__(256) void layernorm_kernel(
    const float* __restrict__ X, const float* __restrict__ gamma,
    const float* __restrict__ beta, float* __restrict__ out)
{
    __shared__ float red_s[8];
    __shared__ float red_ss[8];

    const int row = blockIdx.x;
    const int tid = threadIdx.x;
    const float* x = X + (size_t)row * DQ_;

    float s = 0.f, ss = 0.f;
    #pragma unroll
    for (int i = tid; i < DQ_; i += 256) {
        float v = x[i];
        s += v;
        ss += v * v;
    }
    #pragma unroll
    for (int off = 16; off > 0; off >>= 1) {
        s  += __shfl_xor_sync(0xffffffff, s, off);
        ss += __shfl_xor_sync(0xffffffff, ss, off);
    }
    if ((tid & 31) == 0) {
        red_s[tid >> 5] = s;
        red_ss[tid >> 5] = ss;
    }
    __syncthreads();
    if (tid < 32) {
        float a = (tid < 8) ? red_s[tid] : 0.f;
        float c = (tid < 8) ? red_ss[tid] : 0.f;
        #pragma unroll
        for (int off = 4; off > 0; off >>= 1) {
            a += __shfl_xor_sync(0xffffffff, a, off);
            c += __shfl_xor_sync(0xffffffff, c, off);
        }
        if (tid == 0) { red_s[0] = a; red_ss[0] = c; }
    }
    __syncthreads();

    const float mu = red_s[0] * (1.f / DQ_);
    const float var = red_ss[0] * (1.f / DQ_) - mu * mu;
    const float rstd = rsqrtf(var + EPS_);

    float* orow = out + (size_t)row * DQ_;
    for (int i = tid; i < DQ_; i += 256) {
        orow[i] = (x[i] - mu) * rstd * gamma[i] + beta[i];
    }
}

// ---------------------------------------------------------------------------
// Launch
// ---------------------------------------------------------------------------
extern "C" void kernel_launch(void* const* d_in, const int* in_sizes, int n_in,
                              void* d_out, int out_size)
{
    const float* query     = (const float*)d_in[0];
    const float* key_value = (const float*)d_in[1];
    const float* Wq = (const float*)d_in[2];
    const float* bq = (const float*)d_in[3];
    const float* Wk = (const float*)d_in[4];
    const float* bk = (const float*)d_in[5];
    const float* Wv = (const float*)d_in[6];
    const float* bv = (const float*)d_in[7];
    const float* Wo = (const float*)d_in[8];
    const float* bo = (const float*)d_in[9];
    const float* ln_gamma = (const float*)d_in[10];
    const float* ln_beta  = (const float*)d_in[11];
    float* out = (float*)d_out;

    __nv_bfloat16 *Qin, *KVin, *Wqt, *Wkt, *Wvt, *Wot, *Qp, *Kp, *Vp, *Vt, *Ctx;
    float* X;
    cudaGetSymbolAddress((void**)&Qin, g_Qin);
    cudaGetSymbolAddress((void**)&KVin, g_KVin);
    cudaGetSymbolAddress((void**)&Wqt, g_Wqt);
    cudaGetSymbolAddress((void**)&Wkt, g_Wkt);
    cudaGetSymbolAddress((void**)&Wvt, g_Wvt);
    cudaGetSymbolAddress((void**)&Wot, g_Wot);
    cudaGetSymbolAddress((void**)&Qp, g_Qp);
    cudaGetSymbolAddress((void**)&Kp, g_Kp);
    cudaGetSymbolAddress((void**)&Vp, g_Vp);
    cudaGetSymbolAddress((void**)&Vt, g_Vt);
    cudaGetSymbolAddress((void**)&Ctx, g_Ctx);
    cudaGetSymbolAddress((void**)&X, g_X);

    const int M = B_ * LQ_;   // 4096
    const int K = DQ_;        // 1024
    const int N = HID_;       // 1024

    cudaFuncSetAttribute(gemm_bf16_kernel,
                         cudaFuncAttributeMaxDynamicSharedMemorySize, GEMM_SMEM);
    cudaFuncSetAttribute(attention_bf16_kernel,
                         cudaFuncAttributeMaxDynamicSharedMemorySize, ATT_SMEM);

    // Input conversions
    const int n4 = (M * K) / 4;
    cvt_bf16_kernel<<<n4 / 256, 256>>>(query, Qin, n4);
    cvt_bf16_kernel<<<n4 / 256, 256>>>(key_value, KVin, n4);
    dim3 wgrid(32, 32);
    cvt_transpose_w_kernel<<<wgrid, 256>>>(Wq, Wqt);
    cvt_transpose_w_kernel<<<wgrid, 256>>>(Wk, Wkt);
    cvt_transpose_w_kernel<<<wgrid, 256>>>(Wv, Wvt);
    cvt_transpose_w_kernel<<<wgrid, 256>>>(Wo, Wot);

    dim3 ggrid(N / GBN, M / GBM);

    gemm_bf16_kernel<<<ggrid, 256, GEMM_SMEM>>>(Qin,  Wqt, bq, nullptr, Qp, nullptr, M, N, K);
    gemm_bf16_kernel<<<ggrid, 256, GEMM_SMEM>>>(KVin, Wkt, bk, nullptr, Kp, nullptr, M, N, K);
    gemm_bf16_kernel<<<ggrid, 256, GEMM_SMEM>>>(KVin, Wvt, bv, nullptr, Vp, nullptr, M, N, K);

    dim3 vgrid(LKV_ / 64, NH_, B_);
    transpose_v_kernel<<<vgrid, 256>>>(Vp, Vt);

    dim3 agrid(LQ_ / 128, NH_, B_);
    attention_bf16_kernel<<<agrid, 256, ATT_SMEM>>>(Qp, Kp, Vt, Ctx);

    gemm_bf16_kernel<<<ggrid, 256, GEMM_SMEM>>>(Ctx, Wot, bo, query, nullptr, X, M, DQ_, HID_);

    layernorm_kernel<<<M, 256>>>(X, ln_gamma, ln_beta, out);
}

// round 8
// speedup vs baseline: 1.7358x; 1.0903x over previous
#include <cuda_runtime.h>
#include <cuda_bf16.h>
#include <cstdint>
#include <cstddef>

// Problem constants
#define B_   2
#define LQ_  2048
#define LKV_ 2048
#define DQ_  1024
#define HID_ 1024
#define NH_  16
#define HD_  64
#define EPS_ 1e-5f

// Scratch (allocation-free rule: __device__ globals)
__device__ __nv_bfloat16 g_Qin[B_ * LQ_ * DQ_];
__device__ __nv_bfloat16 g_KVin[B_ * LKV_ * DQ_];
__device__ __nv_bfloat16 g_Wqt[HID_ * DQ_];
__device__ __nv_bfloat16 g_Wkt[HID_ * DQ_];
__device__ __nv_bfloat16 g_Wvt[HID_ * DQ_];
__device__ __nv_bfloat16 g_Wot[DQ_ * HID_];
__device__ __nv_bfloat16 g_Qp[B_ * LQ_ * HID_];
__device__ __nv_bfloat16 g_Kp[B_ * LKV_ * HID_];
__device__ __nv_bfloat16 g_Vp[B_ * LKV_ * HID_];
__device__ __nv_bfloat16 g_Vt[B_ * NH_ * HD_ * LKV_];   // [b][h][d][key]
__device__ __nv_bfloat16 g_Ctx[B_ * LQ_ * HID_];
__device__ float g_X[B_ * LQ_ * DQ_];

// ---------------------------------------------------------------------------
// Helpers
// ---------------------------------------------------------------------------
__device__ __forceinline__ void mma_bf16(float c[4], const uint32_t a[4], const uint32_t b[2]) {
    asm volatile(
        "mma.sync.aligned.m16n8k16.row.col.f32.bf16.bf16.f32 "
        "{%0,%1,%2,%3}, {%4,%5,%6,%7}, {%8,%9}, {%0,%1,%2,%3};\n"
        : "+f"(c[0]), "+f"(c[1]), "+f"(c[2]), "+f"(c[3])
        : "r"(a[0]), "r"(a[1]), "r"(a[2]), "r"(a[3]), "r"(b[0]), "r"(b[1]));
}

__device__ __forceinline__ void ldsm_x4(uint32_t r[4], const __nv_bfloat16* p) {
    uint32_t a = (uint32_t)__cvta_generic_to_shared(p);
    asm volatile("ldmatrix.sync.aligned.m8n8.x4.shared.b16 {%0,%1,%2,%3}, [%4];\n"
        : "=r"(r[0]), "=r"(r[1]), "=r"(r[2]), "=r"(r[3]) : "r"(a));
}

__device__ __forceinline__ uint32_t pack_bf16(float lo, float hi) {
    __nv_bfloat162 p = __floats2bfloat162_rn(lo, hi);
    return *(uint32_t*)&p;
}

__device__ __forceinline__ void cp_async16(void* smem_dst, const void* gsrc) {
    uint32_t s = (uint32_t)__cvta_generic_to_shared(smem_dst);
    asm volatile("cp.async.cg.shared.global [%0], [%1], 16;\n" :: "r"(s), "l"(gsrc));
}
__device__ __forceinline__ void cp_commit() {
    asm volatile("cp.async.commit_group;\n");
}
template <int N>
__device__ __forceinline__ void cp_wait() {
    asm volatile("cp.async.wait_group %0;\n" :: "n"(N));
}

// FMA-only 2^x (no MUFU). |err| ~ 2e-6 rel.
__device__ __forceinline__ float exp2_fast(float x) {
    x = fmaxf(x, -120.f);
    float t = x + 12582912.f;
    int n = __float_as_int(t) - 0x4B400000;
    float f = x - (t - 12582912.f);
    float p = 1.33335581e-3f;
    p = fmaf(p, f, 9.61812910e-3f);
    p = fmaf(p, f, 5.55041087e-2f);
    p = fmaf(p, f, 2.40226507e-1f);
    p = fmaf(p, f, 6.93147182e-1f);
    p = fmaf(p, f, 1.0f);
    return __int_as_float(__float_as_int(p) + (n << 23));
}

// ---------------------------------------------------------------------------
// Conversion kernels (consolidated launches via grid.z)
// ---------------------------------------------------------------------------
__global__ __launch_bounds__(256) void cvt_bf16_kernel(
    const float* __restrict__ in0, __nv_bfloat16* __restrict__ out0,
    const float* __restrict__ in1, __nv_bfloat16* __restrict__ out1, int n4)
{
    int t = blockIdx.x * 256 + threadIdx.x;
    const float* in = blockIdx.z ? in1 : in0;
    __nv_bfloat16* out = blockIdx.z ? out1 : out0;
    if (t < n4) {
        float4 v = *(const float4*)&in[4 * t];
        uint2 o;
        o.x = pack_bf16(v.x, v.y);
        o.y = pack_bf16(v.z, v.w);
        *(uint2*)&out[4 * t] = o;
    }
}

// W[K][N] f32 -> Wt[N][K] bf16  (K = N = 1024), 4 weights in one launch
__global__ __launch_bounds__(256) void cvt_transpose_w_kernel(
    const float* __restrict__ W0, __nv_bfloat16* __restrict__ T0,
    const float* __restrict__ W1, __nv_bfloat16* __restrict__ T1,
    const float* __restrict__ W2, __nv_bfloat16* __restrict__ T2,
    const float* __restrict__ W3, __nv_bfloat16* __restrict__ T3)
{
    __shared__ float tile[32][33];
    const float* W;
    __nv_bfloat16* Wt;
    switch (blockIdx.z) {
        case 0: W = W0; Wt = T0; break;
        case 1: W = W1; Wt = T1; break;
        case 2: W = W2; Wt = T2; break;
        default: W = W3; Wt = T3; break;
    }
    const int tx = threadIdx.x & 31;
    const int ty = threadIdx.x >> 5;
    const int k0 = blockIdx.y * 32;
    const int n0 = blockIdx.x * 32;
    #pragma unroll
    for (int i = 0; i < 4; i++)
        tile[ty + 8 * i][tx] = W[(size_t)(k0 + ty + 8 * i) * 1024 + n0 + tx];
    __syncthreads();
    #pragma unroll
    for (int i = 0; i < 4; i++)
        Wt[(size_t)(n0 + ty + 8 * i) * 1024 + k0 + tx] =
            __float2bfloat16(tile[tx][ty + 8 * i]);
}

// Vp [b][key][h*64+d] bf16 -> Vt [b][h][d][key] bf16
__global__ __launch_bounds__(256) void transpose_v_kernel(
    const __nv_bfloat16* __restrict__ Vp, __nv_bfloat16* __restrict__ Vt)
{
    __shared__ __nv_bfloat16 tile[64][65];
    const int tid = threadIdx.x;
    const int b = blockIdx.z, h = blockIdx.y;
    const int kt = blockIdx.x * 64;
    #pragma unroll
    for (int i = 0; i < 2; i++) {
        int q = tid + 256 * i;
        int r = q >> 3, c = (q & 7) * 8;
        uint4 v = *(const uint4*)&Vp[(size_t)(b * LKV_ + kt + r) * HID_ + h * HD_ + c];
        const __nv_bfloat16* e = (const __nv_bfloat16*)&v;
        #pragma unroll
        for (int j = 0; j < 8; j++) tile[r][c + j] = e[j];
    }
    __syncthreads();
    #pragma unroll
    for (int i = 0; i < 2; i++) {
        int q = tid + 256 * i;
        int d = q >> 3, c = (q & 7) * 8;
        __nv_bfloat16 e[8];
        #pragma unroll
        for (int j = 0; j < 8; j++) e[j] = tile[c + j][d];
        *(uint4*)&Vt[(size_t)((b * NH_ + h) * HD_ + d) * LKV_ + kt + c] = *(uint4*)e;
    }
}

// ---------------------------------------------------------------------------
// BF16 GEMM: C[M,N] = A[M,K] @ Wt[N,K]^T + bias (+ residual)
// Block 128x128, BK=32, 256 threads (8 warps 2x4), warp tile 64x32.
// cp.async double buffer; ldmatrix fragment loads.
// ---------------------------------------------------------------------------
#define GBM 128
#define GBN 128
#define GBK 32
#define GLD 40
#define TILE_STG (128 * GLD)
#define GEMM_SMEM (4 * TILE_STG * 2)

__global__ __launch_bounds__(256) void gemm_bf16_kernel(
    const __nv_bfloat16* __restrict__ A, const __nv_bfloat16* __restrict__ Wt,
    const float* __restrict__ bias, const float* __restrict__ residual,
    __nv_bfloat16* __restrict__ Cb, float* __restrict__ Cf,
    int M, int N, int K)
{
    extern __shared__ __nv_bfloat16 gsm[];
    __nv_bfloat16* AsB = gsm;
    __nv_bfloat16* BsB = gsm + 2 * TILE_STG;

    const int tid  = threadIdx.x;
    const int lane = tid & 31;
    const int warp = tid >> 5;
    const int warpRow = (warp >> 2) * 64;
    const int warpCol = (warp & 3) * 32;
    const int row0 = blockIdx.y * GBM;
    const int col0 = blockIdx.x * GBN;
    const int r0 = lane >> 2, qd = lane & 3;

    // ldmatrix lane offsets
    const int aLOff = (warpRow + (lane & 15)) * GLD + (lane >> 4) * 8;             // A frags
    const int bLOff = (warpCol + (lane >> 4) * 8 + (lane & 7)) * GLD + ((lane >> 3) & 1) * 8;  // B frags

    float cf[4][4][4];
    #pragma unroll
    for (int mt = 0; mt < 4; mt++)
        #pragma unroll
        for (int nt = 0; nt < 4; nt++)
            #pragma unroll
            for (int i = 0; i < 4; i++) cf[mt][nt][i] = 0.f;

    const int nT = K / GBK;

    auto fill = [&](int s, int k0) {
        __nv_bfloat16* As = AsB + s * TILE_STG;
        __nv_bfloat16* Bs = BsB + s * TILE_STG;
        #pragma unroll
        for (int i = 0; i < 2; i++) {
            int q = tid + 256 * i;
            int r = q >> 2, c = (q & 3) * 8;
            cp_async16(&As[r * GLD + c], &A[(size_t)(row0 + r) * K + k0 + c]);
        }
        #pragma unroll
        for (int i = 0; i < 2; i++) {
            int q = tid + 256 * i;
            int r = q >> 2, c = (q & 3) * 8;
            cp_async16(&Bs[r * GLD + c], &Wt[(size_t)(col0 + r) * K + k0 + c]);
        }
    };

    fill(0, 0);
    cp_commit();

    for (int t = 0; t < nT; t++) {
        if (t + 1 < nT) fill((t + 1) & 1, (t + 1) * GBK);
        cp_commit();
        cp_wait<1>();
        __syncthreads();

        const __nv_bfloat16* As = AsB + (t & 1) * TILE_STG + aLOff;
        const __nv_bfloat16* Bs = BsB + (t & 1) * TILE_STG + bLOff;

        #pragma unroll
        for (int ks = 0; ks < 2; ks++) {
            uint32_t af[4][4], bf[2][4];
            #pragma unroll
            for (int mt = 0; mt < 4; mt++)
                ldsm_x4(af[mt], As + 16 * mt * GLD + 16 * ks);
            #pragma unroll
            for (int ntp = 0; ntp < 2; ntp++)
                ldsm_x4(bf[ntp], Bs + 16 * ntp * GLD + 16 * ks);
            #pragma unroll
            for (int mt = 0; mt < 4; mt++)
                #pragma unroll
                for (int ntp = 0; ntp < 2; ntp++) {
                    mma_bf16(cf[mt][2 * ntp],     af[mt], &bf[ntp][0]);
                    mma_bf16(cf[mt][2 * ntp + 1], af[mt], &bf[ntp][2]);
                }
        }
        __syncthreads();
    }

    // Epilogue
    #pragma unroll
    for (int mt = 0; mt < 4; mt++) {
        int r  = row0 + warpRow + 16 * mt + r0;
        int r2 = r + 8;
        #pragma unroll
        for (int nt = 0; nt < 4; nt++) {
            int c = col0 + warpCol + 8 * nt + 2 * qd;
            float b0 = bias[c], b1 = bias[c + 1];
            float v0 = cf[mt][nt][0] + b0, v1 = cf[mt][nt][1] + b1;
            float v2 = cf[mt][nt][2] + b0, v3 = cf[mt][nt][3] + b1;
            if (Cb) {
                *(uint32_t*)&Cb[(size_t)r  * N + c] = pack_bf16(v0, v1);
                *(uint32_t*)&Cb[(size_t)r2 * N + c] = pack_bf16(v2, v3);
            } else {
                v0 += residual[(size_t)r  * N + c];
                v1 += residual[(size_t)r  * N + c + 1];
                v2 += residual[(size_t)r2 * N + c];
                v3 += residual[(size_t)r2 * N + c + 1];
                *(float2*)&Cf[(size_t)r  * N + c] = make_float2(v0, v1);
                *(float2*)&Cf[(size_t)r2 * N + c] = make_float2(v2, v3);
            }
        }
    }
}

// ---------------------------------------------------------------------------
// Flash attention, bf16 m16n8k16 with ldmatrix. 256 threads, 128 q/block.
// KV tile 64. P stays in registers; V from pre-transposed g_Vt.
// ---------------------------------------------------------------------------
#define KS_LD 72
#define ATT_STG (64 * KS_LD)
#define ATT_SMEM (4 * ATT_STG * 2)

__global__ __launch_bounds__(256) void attention_bf16_kernel(
    const __nv_bfloat16* __restrict__ Qp, const __nv_bfloat16* __restrict__ Kp,
    const __nv_bfloat16* __restrict__ Vt, __nv_bfloat16* __restrict__ Ctx)
{
    extern __shared__ __nv_bfloat16 asmem[];
    __nv_bfloat16* KsB  = asmem;
    __nv_bfloat16* VtsB = asmem + 2 * ATT_STG;

    const int tid  = threadIdx.x;
    const int lane = tid & 31;
    const int warp = tid >> 5;
    const int r0 = lane >> 2, qd = lane & 3;
    const int b  = blockIdx.z;
    const int h  = blockIdx.y;
    const int q0 = blockIdx.x * 128;
    const int lr = warp * 16 + r0;
    const float SC = 0.125f * 1.44269504089f;

    // ldmatrix lane offset for B-operand loads (keys or d-rows)
    const int bLOff = ((lane >> 4) * 8 + (lane & 7)) * KS_LD + ((lane >> 3) & 1) * 8;

    // Q fragments from GMEM
    uint32_t qf[4][4];
    {
        const __nv_bfloat16* q0p = Qp + ((size_t)(b * LQ_ + q0 + lr) * HID_ + h * HD_);
        const __nv_bfloat16* q1p = q0p + (size_t)8 * HID_;
        #pragma unroll
        for (int ks = 0; ks < 4; ks++) {
            int c = 16 * ks + 2 * qd;
            qf[ks][0] = *(const uint32_t*)&q0p[c];
            qf[ks][1] = *(const uint32_t*)&q1p[c];
            qf[ks][2] = *(const uint32_t*)&q0p[c + 8];
            qf[ks][3] = *(const uint32_t*)&q1p[c + 8];
        }
    }

    float of[8][4];
    #pragma unroll
    for (int nt = 0; nt < 8; nt++)
        #pragma unroll
        for (int i = 0; i < 4; i++) of[nt][i] = 0.f;
    float m0 = -1e30f, m1 = -1e30f, l0 = 0.f, l1 = 0.f;

    const __nv_bfloat16* Kbase  = Kp + ((size_t)b * LKV_ * HID_ + h * HD_);
    const __nv_bfloat16* Vtbase = Vt + ((size_t)(b * NH_ + h) * HD_) * LKV_;

    auto fill = [&](int s, int kt) {
        __nv_bfloat16* Ks  = KsB + s * ATT_STG;
        __nv_bfloat16* Vts = VtsB + s * ATT_STG;
        #pragma unroll
        for (int i = 0; i < 2; i++) {
            int q = tid + 256 * i;
            int r = q >> 3, c = (q & 7) * 8;
            cp_async16(&Ks[r * KS_LD + c], &Kbase[(size_t)(kt + r) * HID_ + c]);
        }
        #pragma unroll
        for (int i = 0; i < 2; i++) {
            int q = tid + 256 * i;
            int d = q >> 3, c = (q & 7) * 8;
            cp_async16(&Vts[d * KS_LD + c], &Vtbase[(size_t)d * LKV_ + kt + c]);
        }
    };

    fill(0, 0);
    cp_commit();

    const int nT = LKV_ / 64;
    for (int t = 0; t < nT; t++) {
        if (t + 1 < nT) fill((t + 1) & 1, (t + 1) * 64);
        cp_commit();
        cp_wait<1>();
        __syncthreads();

        const __nv_bfloat16* Ks  = KsB + (t & 1) * ATT_STG + bLOff;
        const __nv_bfloat16* Vts = VtsB + (t & 1) * ATT_STG + bLOff;

        // S = Q @ K^T
        float sf[8][4];
        #pragma unroll
        for (int nt = 0; nt < 8; nt++)
            #pragma unroll
            for (int i = 0; i < 4; i++) sf[nt][i] = 0.f;
        #pragma unroll
        for (int ks = 0; ks < 4; ks++) {
            #pragma unroll
            for (int ntp = 0; ntp < 4; ntp++) {
                uint32_t kr[4];
                ldsm_x4(kr, Ks + 16 * ntp * KS_LD + 16 * ks);
                mma_bf16(sf[2 * ntp],     qf[ks], &kr[0]);
                mma_bf16(sf[2 * ntp + 1], qf[ks], &kr[2]);
            }
        }

        // Online softmax in exp2 domain
        float mloc0 = -1e30f, mloc1 = -1e30f;
        #pragma unroll
        for (int nt = 0; nt < 8; nt++) {
            mloc0 = fmaxf(mloc0, fmaxf(sf[nt][0], sf[nt][1]));
            mloc1 = fmaxf(mloc1, fmaxf(sf[nt][2], sf[nt][3]));
        }
        mloc0 = fmaxf(mloc0, __shfl_xor_sync(0xffffffff, mloc0, 1));
        mloc0 = fmaxf(mloc0, __shfl_xor_sync(0xffffffff, mloc0, 2));
        mloc1 = fmaxf(mloc1, __shfl_xor_sync(0xffffffff, mloc1, 1));
        mloc1 = fmaxf(mloc1, __shfl_xor_sync(0xffffffff, mloc1, 2));

        float mn0 = fmaxf(m0, mloc0), mn1 = fmaxf(m1, mloc1);
        float corr0 = exp2_fast((m0 - mn0) * SC);
        float corr1 = exp2_fast((m1 - mn1) * SC);
        m0 = mn0; m1 = mn1;

        float rs0 = 0.f, rs1 = 0.f;
        float pv[8][4];
        #pragma unroll
        for (int nt = 0; nt < 8; nt++) {
            pv[nt][0] = exp2_fast((sf[nt][0] - mn0) * SC);
            pv[nt][1] = exp2_fast((sf[nt][1] - mn0) * SC);
            pv[nt][2] = exp2_fast((sf[nt][2] - mn1) * SC);
            pv[nt][3] = exp2_fast((sf[nt][3] - mn1) * SC);
            rs0 += pv[nt][0] + pv[nt][1];
            rs1 += pv[nt][2] + pv[nt][3];
        }
        rs0 += __shfl_xor_sync(0xffffffff, rs0, 1);
        rs0 += __shfl_xor_sync(0xffffffff, rs0, 2);
        rs1 += __shfl_xor_sync(0xffffffff, rs1, 1);
        rs1 += __shfl_xor_sync(0xffffffff, rs1, 2);
        l0 = l0 * corr0 + rs0;
        l1 = l1 * corr1 + rs1;

        #pragma unroll
        for (int nt = 0; nt < 8; nt++) {
            of[nt][0] *= corr0; of[nt][1] *= corr0;
            of[nt][2] *= corr1; of[nt][3] *= corr1;
        }

        // P A-fragments from registers
        uint32_t pf[4][4];
        #pragma unroll
        for (int ks = 0; ks < 4; ks++) {
            pf[ks][0] = pack_bf16(pv[2 * ks][0],     pv[2 * ks][1]);
            pf[ks][1] = pack_bf16(pv[2 * ks][2],     pv[2 * ks][3]);
            pf[ks][2] = pack_bf16(pv[2 * ks + 1][0], pv[2 * ks + 1][1]);
            pf[ks][3] = pack_bf16(pv[2 * ks + 1][2], pv[2 * ks + 1][3]);
        }

        // O += P @ V
        #pragma unroll
        for (int ks = 0; ks < 4; ks++) {
            #pragma unroll
            for (int ntp = 0; ntp < 4; ntp++) {
                uint32_t vr[4];
                ldsm_x4(vr, Vts + 16 * ntp * KS_LD + 16 * ks);
                mma_bf16(of[2 * ntp],     pf[ks], &vr[0]);
                mma_bf16(of[2 * ntp + 1], pf[ks], &vr[2]);
            }
        }
        __syncthreads();
    }

    // Normalize + store Ctx (bf16)
    float inv0 = 1.f / l0, inv1 = 1.f / l1;
    __nv_bfloat16* o0p = Ctx + ((size_t)(b * LQ_ + q0 + lr) * HID_ + h * HD_);
    __nv_bfloat16* o1p = o0p + (size_t)8 * HID_;
    #pragma unroll
    for (int nt = 0; nt < 8; nt++) {
        int c = 8 * nt + 2 * qd;
        *(uint32_t*)&o0p[c] = pack_bf16(of[nt][0] * inv0, of[nt][1] * inv0);
        *(uint32_t*)&o1p[c] = pack_bf16(of[nt][2] * inv1, of[nt][3] * inv1);
    }
}

// ---------------------------------------------------------------------------
// LayerNorm over rows of 1024. One block (256 threads) per row.
// ---------------------------------------------------------------------------
__global__ __launch_bounds__(256) void layernorm_kernel(
    const float* __restrict__ X, const float* __restrict__ gamma,
    const float* __restrict__ beta, float* __restrict__ out)
{
    __shared__ float red_s[8];
    __shared__ float red_ss[8];

    const int row = blockIdx.x;
    const int tid = threadIdx.x;
    const float* x = X + (size_t)row * DQ_;

    float s = 0.f, ss = 0.f;
    #pragma unroll
    for (int i = tid; i < DQ_; i += 256) {
        float v = x[i];
        s += v;
        ss += v * v;
    }
    #pragma unroll
    for (int off = 16; off > 0; off >>= 1) {
        s  += __shfl_xor_sync(0xffffffff, s, off);
        ss += __shfl_xor_sync(0xffffffff, ss, off);
    }
    if ((tid & 31) == 0) {
        red_s[tid >> 5] = s;
        red_ss[tid >> 5] = ss;
    }
    __syncthreads();
    if (tid < 32) {
        float a = (tid < 8) ? red_s[tid] : 0.f;
        float c = (tid < 8) ? red_ss[tid] : 0.f;
        #pragma unroll
        for (int off = 4; off > 0; off >>= 1) {
            a += __shfl_xor_sync(0xffffffff, a, off);
            c += __shfl_xor_sync(0xffffffff, c, off);
        }
        if (tid == 0) { red_s[0] = a; red_ss[0] = c; }
    }
    __syncthreads();

    const float mu = red_s[0] * (1.f / DQ_);
    const float var = red_ss[0] * (1.f / DQ_) - mu * mu;
    const float rstd = rsqrtf(var + EPS_);

    float* orow = out + (size_t)row * DQ_;
    for (int i = tid; i < DQ_; i += 256) {
        orow[i] = (x[i] - mu) * rstd * gamma[i] + beta[i];
    }
}

// ---------------------------------------------------------------------------
// Launch
// ---------------------------------------------------------------------------
extern "C" void kernel_launch(void* const* d_in, const int* in_sizes, int n_in,
                              void* d_out, int out_size)
{
    const float* query     = (const float*)d_in[0];
    const float* key_value = (const float*)d_in[1];
    const float* Wq = (const float*)d_in[2];
    const float* bq = (const float*)d_in[3];
    const float* Wk = (const float*)d_in[4];
    const float* bk = (const float*)d_in[5];
    const float* Wv = (const float*)d_in[6];
    const float* bv = (const float*)d_in[7];
    const float* Wo = (const float*)d_in[8];
    const float* bo = (const float*)d_in[9];
    const float* ln_gamma = (const float*)d_in[10];
    const float* ln_beta  = (const float*)d_in[11];
    float* out = (float*)d_out;

    __nv_bfloat16 *Qin, *KVin, *Wqt, *Wkt, *Wvt, *Wot, *Qp, *Kp, *Vp, *Vt, *Ctx;
    float* X;
    cudaGetSymbolAddress((void**)&Qin, g_Qin);
    cudaGetSymbolAddress((void**)&KVin, g_KVin);
    cudaGetSymbolAddress((void**)&Wqt, g_Wqt);
    cudaGetSymbolAddress((void**)&Wkt, g_Wkt);
    cudaGetSymbolAddress((void**)&Wvt, g_Wvt);
    cudaGetSymbolAddress((void**)&Wot, g_Wot);
    cudaGetSymbolAddress((void**)&Qp, g_Qp);
    cudaGetSymbolAddress((void**)&Kp, g_Kp);
    cudaGetSymbolAddress((void**)&Vp, g_Vp);
    cudaGetSymbolAddress((void**)&Vt, g_Vt);
    cudaGetSymbolAddress((void**)&Ctx, g_Ctx);
    cudaGetSymbolAddress((void**)&X, g_X);

    const int M = B_ * LQ_;
    const int K = DQ_;
    const int N = HID_;

    cudaFuncSetAttribute(gemm_bf16_kernel,
                         cudaFuncAttributeMaxDynamicSharedMemorySize, GEMM_SMEM);
    cudaFuncSetAttribute(attention_bf16_kernel,
                         cudaFuncAttributeMaxDynamicSharedMemorySize, ATT_SMEM);

    // Input conversions (consolidated)
    const int n4 = (M * K) / 4;
    dim3 cgrid(n4 / 256, 1, 2);
    cvt_bf16_kernel<<<cgrid, 256>>>(query, Qin, key_value, KVin, n4);
    dim3 wgrid(32, 32, 4);
    cvt_transpose_w_kernel<<<wgrid, 256>>>(Wq, Wqt, Wk, Wkt, Wv, Wvt, Wo, Wot);

    dim3 ggrid(N / GBN, M / GBM);

    gemm_bf16_kernel<<<ggrid, 256, GEMM_SMEM>>>(Qin,  Wqt, bq, nullptr, Qp, nullptr, M, N, K);
    gemm_bf16_kernel<<<ggrid, 256, GEMM_SMEM>>>(KVin, Wkt, bk, nullptr, Kp, nullptr, M, N, K);
    gemm_bf16_kernel<<<ggrid, 256, GEMM_SMEM>>>(KVin, Wvt, bv, nullptr, Vp, nullptr, M, N, K);

    dim3 vgrid(LKV_ / 64, NH_, B_);
    transpose_v_kernel<<<vgrid, 256>>>(Vp, Vt);

    dim3 agrid(LQ_ / 128, NH_, B_);
    attention_bf16_kernel<<<agrid, 256, ATT_SMEM>>>(Qp, Kp, Vt, Ctx);

    gemm_bf16_kernel<<<ggrid, 256, GEMM_SMEM>>>(Ctx, Wot, bo, query, nullptr, X, M, DQ_, HID_);

    layernorm_kernel<<<M, 256>>>(X, ln_gamma, ln_beta, out);
}

// round 13
// speedup vs baseline: 1.7747x; 1.0224x over previous
#include <cuda_runtime.h>
#include <cuda_bf16.h>
#include <cstdint>
#include <cstddef>

// Problem constants
#define B_   2
#define LQ_  2048
#define LKV_ 2048
#define DQ_  1024
#define HID_ 1024
#define NH_  16
#define HD_  64
#define EPS_ 1e-5f

// Scratch (allocation-free rule: __device__ globals)
__device__ __nv_bfloat16 g_Qin[B_ * LQ_ * DQ_];
__device__ __nv_bfloat16 g_KVin[B_ * LKV_ * DQ_];
__device__ __nv_bfloat16 g_Wqt[HID_ * DQ_];
__device__ __nv_bfloat16 g_Wkt[HID_ * DQ_];
__device__ __nv_bfloat16 g_Wvt[HID_ * DQ_];
__device__ __nv_bfloat16 g_Wot[DQ_ * HID_];
__device__ __nv_bfloat16 g_Qp[B_ * LQ_ * HID_];
__device__ __nv_bfloat16 g_Kp[B_ * LKV_ * HID_];
__device__ __nv_bfloat16 g_Vp[B_ * LKV_ * HID_];
__device__ __nv_bfloat16 g_Vt[B_ * NH_ * HD_ * LKV_];   // [b][h][d][key]
__device__ __nv_bfloat16 g_Ctx[B_ * LQ_ * HID_];
__device__ float g_X[B_ * LQ_ * DQ_];

// ---------------------------------------------------------------------------
// Helpers
// ---------------------------------------------------------------------------
__device__ __forceinline__ void mma_bf16(float c[4], const uint32_t a[4], const uint32_t b[2]) {
    asm volatile(
        "mma.sync.aligned.m16n8k16.row.col.f32.bf16.bf16.f32 "
        "{%0,%1,%2,%3}, {%4,%5,%6,%7}, {%8,%9}, {%0,%1,%2,%3};\n"
        : "+f"(c[0]), "+f"(c[1]), "+f"(c[2]), "+f"(c[3])
        : "r"(a[0]), "r"(a[1]), "r"(a[2]), "r"(a[3]), "r"(b[0]), "r"(b[1]));
}

__device__ __forceinline__ void ldsm_x4(uint32_t r[4], const __nv_bfloat16* p) {
    uint32_t a = (uint32_t)__cvta_generic_to_shared(p);
    asm volatile("ldmatrix.sync.aligned.m8n8.x4.shared.b16 {%0,%1,%2,%3}, [%4];\n"
        : "=r"(r[0]), "=r"(r[1]), "=r"(r[2]), "=r"(r[3]) : "r"(a));
}

__device__ __forceinline__ uint32_t pack_bf16(float lo, float hi) {
    __nv_bfloat162 p = __floats2bfloat162_rn(lo, hi);
    return *(uint32_t*)&p;
}

__device__ __forceinline__ void cp_async16(void* smem_dst, const void* gsrc) {
    uint32_t s = (uint32_t)__cvta_generic_to_shared(smem_dst);
    asm volatile("cp.async.cg.shared.global [%0], [%1], 16;\n" :: "r"(s), "l"(gsrc));
}
__device__ __forceinline__ void cp_commit() {
    asm volatile("cp.async.commit_group;\n");
}
template <int N>
__device__ __forceinline__ void cp_wait() {
    asm volatile("cp.async.wait_group %0;\n" :: "n"(N));
}

// FMA-only 2^x (no MUFU). |err| ~ 2e-6 rel.
__device__ __forceinline__ float exp2_fast(float x) {
    x = fmaxf(x, -120.f);
    float t = x + 12582912.f;
    int n = __float_as_int(t) - 0x4B400000;
    float f = x - (t - 12582912.f);
    float p = 1.33335581e-3f;
    p = fmaf(p, f, 9.61812910e-3f);
    p = fmaf(p, f, 5.55041087e-2f);
    p = fmaf(p, f, 2.40226507e-1f);
    p = fmaf(p, f, 6.93147182e-1f);
    p = fmaf(p, f, 1.0f);
    return __int_as_float(__float_as_int(p) + (n << 23));
}

// ---------------------------------------------------------------------------
// Conversion kernels (consolidated launches via grid.z)
// ---------------------------------------------------------------------------
__global__ __launch_bounds__(256) void cvt_bf16_kernel(
    const float* __restrict__ in0, __nv_bfloat16* __restrict__ out0,
    const float* __restrict__ in1, __nv_bfloat16* __restrict__ out1, int n4)
{
    int t = blockIdx.x * 256 + threadIdx.x;
    const float* in = blockIdx.z ? in1 : in0;
    __nv_bfloat16* out = blockIdx.z ? out1 : out0;
    if (t < n4) {
        float4 v = *(const float4*)&in[4 * t];
        uint2 o;
        o.x = pack_bf16(v.x, v.y);
        o.y = pack_bf16(v.z, v.w);
        *(uint2*)&out[4 * t] = o;
    }
}

// W[K][N] f32 -> Wt[N][K] bf16  (K = N = 1024), 4 weights in one launch
__global__ __launch_bounds__(256) void cvt_transpose_w_kernel(
    const float* __restrict__ W0, __nv_bfloat16* __restrict__ T0,
    const float* __restrict__ W1, __nv_bfloat16* __restrict__ T1,
    const float* __restrict__ W2, __nv_bfloat16* __restrict__ T2,
    const float* __restrict__ W3, __nv_bfloat16* __restrict__ T3)
{
    __shared__ float tile[32][33];
    const float* W;
    __nv_bfloat16* Wt;
    switch (blockIdx.z) {
        case 0: W = W0; Wt = T0; break;
        case 1: W = W1; Wt = T1; break;
        case 2: W = W2; Wt = T2; break;
        default: W = W3; Wt = T3; break;
    }
    const int tx = threadIdx.x & 31;
    const int ty = threadIdx.x >> 5;
    const int k0 = blockIdx.y * 32;
    const int n0 = blockIdx.x * 32;
    #pragma unroll
    for (int i = 0; i < 4; i++)
        tile[ty + 8 * i][tx] = W[(size_t)(k0 + ty + 8 * i) * 1024 + n0 + tx];
    __syncthreads();
    #pragma unroll
    for (int i = 0; i < 4; i++)
        Wt[(size_t)(n0 + ty + 8 * i) * 1024 + k0 + tx] =
            __float2bfloat16(tile[tx][ty + 8 * i]);
}

// Vp [b][key][h*64+d] bf16 -> Vt [b][h][d][key] bf16
__global__ __launch_bounds__(256) void transpose_v_kernel(
    const __nv_bfloat16* __restrict__ Vp, __nv_bfloat16* __restrict__ Vt)
{
    __shared__ __nv_bfloat16 tile[64][65];
    const int tid = threadIdx.x;
    const int b = blockIdx.z, h = blockIdx.y;
    const int kt = blockIdx.x * 64;
    #pragma unroll
    for (int i = 0; i < 2; i++) {
        int q = tid + 256 * i;
        int r = q >> 3, c = (q & 7) * 8;
        uint4 v = *(const uint4*)&Vp[(size_t)(b * LKV_ + kt + r) * HID_ + h * HD_ + c];
        const __nv_bfloat16* e = (const __nv_bfloat16*)&v;
        #pragma unroll
        for (int j = 0; j < 8; j++) tile[r][c + j] = e[j];
    }
    __syncthreads();
    #pragma unroll
    for (int i = 0; i < 2; i++) {
        int q = tid + 256 * i;
        int d = q >> 3, c = (q & 7) * 8;
        __nv_bfloat16 e[8];
        #pragma unroll
        for (int j = 0; j < 8; j++) e[j] = tile[c + j][d];
        *(uint4*)&Vt[(size_t)((b * NH_ + h) * HD_ + d) * LKV_ + kt + c] = *(uint4*)e;
    }
}

// ---------------------------------------------------------------------------
// BF16 GEMM body: C[M,N] = A[M,K] @ Wt[N,K]^T + bias (+ residual)
// Block 128x128, BK=32, 256 threads (8 warps 2x4), warp tile 64x32.
// cp.async 3-stage pipeline; ldmatrix fragment loads.
// ---------------------------------------------------------------------------
#define GBM 128
#define GBN 128
#define GBK 32
#define GLD 40
#define NSTG 3
#define TILE_STG (128 * GLD)
#define GEMM_SMEM (2 * NSTG * TILE_STG * 2)   // A+B stages, bytes

__device__ __forceinline__ void gemm_body(
    const __nv_bfloat16* __restrict__ A, const __nv_bfloat16* __restrict__ Wt,
    const float* __restrict__ bias, const float* __restrict__ residual,
    __nv_bfloat16* __restrict__ Cb, float* __restrict__ Cf,
    int M, int N, int K)
{
    extern __shared__ __nv_bfloat16 gsm[];
    __nv_bfloat16* AsB = gsm;                      // [NSTG][TILE_STG]
    __nv_bfloat16* BsB = gsm + NSTG * TILE_STG;    // [NSTG][TILE_STG]

    const int tid  = threadIdx.x;
    const int lane = tid & 31;
    const int warp = tid >> 5;
    const int warpRow = (warp >> 2) * 64;
    const int warpCol = (warp & 3) * 32;
    const int row0 = blockIdx.y * GBM;
    const int col0 = blockIdx.x * GBN;
    const int r0 = lane >> 2, qd = lane & 3;

    // ldmatrix lane offsets
    const int aLOff = (warpRow + (lane & 15)) * GLD + (lane >> 4) * 8;
    const int bLOff = (warpCol + (lane >> 4) * 8 + (lane & 7)) * GLD + ((lane >> 3) & 1) * 8;

    float cf[4][4][4];
    #pragma unroll
    for (int mt = 0; mt < 4; mt++)
        #pragma unroll
        for (int nt = 0; nt < 4; nt++)
            #pragma unroll
            for (int i = 0; i < 4; i++) cf[mt][nt][i] = 0.f;

    const int nT = K / GBK;

    auto fill = [&](int s, int k0) {
        __nv_bfloat16* As = AsB + s * TILE_STG;
        __nv_bfloat16* Bs = BsB + s * TILE_STG;
        #pragma unroll
        for (int i = 0; i < 2; i++) {
            int q = tid + 256 * i;
            int r = q >> 2, c = (q & 3) * 8;
            cp_async16(&As[r * GLD + c], &A[(size_t)(row0 + r) * K + k0 + c]);
        }
        #pragma unroll
        for (int i = 0; i < 2; i++) {
            int q = tid + 256 * i;
            int r = q >> 2, c = (q & 3) * 8;
            cp_async16(&Bs[r * GLD + c], &Wt[(size_t)(col0 + r) * K + k0 + c]);
        }
    };

    // Prologue: fill NSTG-1 stages
    fill(0, 0);
    cp_commit();
    fill(1, GBK);
    cp_commit();

    for (int t = 0; t < nT; t++) {
        if (t + NSTG - 1 < nT) fill((t + NSTG - 1) % NSTG, (t + NSTG - 1) * GBK);
        cp_commit();
        cp_wait<NSTG - 1>();
        __syncthreads();

        const __nv_bfloat16* As = AsB + (t % NSTG) * TILE_STG + aLOff;
        const __nv_bfloat16* Bs = BsB + (t % NSTG) * TILE_STG + bLOff;

        #pragma unroll
        for (int ks = 0; ks < 2; ks++) {
            uint32_t af[4][4], bf[2][4];
            #pragma unroll
            for (int mt = 0; mt < 4; mt++)
                ldsm_x4(af[mt], As + 16 * mt * GLD + 16 * ks);
            #pragma unroll
            for (int ntp = 0; ntp < 2; ntp++)
                ldsm_x4(bf[ntp], Bs + 16 * ntp * GLD + 16 * ks);
            #pragma unroll
            for (int mt = 0; mt < 4; mt++)
                #pragma unroll
                for (int ntp = 0; ntp < 2; ntp++) {
                    mma_bf16(cf[mt][2 * ntp],     af[mt], &bf[ntp][0]);
                    mma_bf16(cf[mt][2 * ntp + 1], af[mt], &bf[ntp][2]);
                }
        }
        __syncthreads();
    }

    // Epilogue
    #pragma unroll
    for (int mt = 0; mt < 4; mt++) {
        int r  = row0 + warpRow + 16 * mt + r0;
        int r2 = r + 8;
        #pragma unroll
        for (int nt = 0; nt < 4; nt++) {
            int c = col0 + warpCol + 8 * nt + 2 * qd;
            float b0 = bias[c], b1 = bias[c + 1];
            float v0 = cf[mt][nt][0] + b0, v1 = cf[mt][nt][1] + b1;
            float v2 = cf[mt][nt][2] + b0, v3 = cf[mt][nt][3] + b1;
            if (Cb) {
                *(uint32_t*)&Cb[(size_t)r  * N + c] = pack_bf16(v0, v1);
                *(uint32_t*)&Cb[(size_t)r2 * N + c] = pack_bf16(v2, v3);
            } else {
                v0 += residual[(size_t)r  * N + c];
                v1 += residual[(size_t)r  * N + c + 1];
                v2 += residual[(size_t)r2 * N + c];
                v3 += residual[(size_t)r2 * N + c + 1];
                *(float2*)&Cf[(size_t)r  * N + c] = make_float2(v0, v1);
                *(float2*)&Cf[(size_t)r2 * N + c] = make_float2(v2, v3);
            }
        }
    }
}

// Fused Q/K/V projections: grid.z in {0,1,2} selects operand set.
__global__ __launch_bounds__(256) void gemm_qkv_kernel(
    const __nv_bfloat16* __restrict__ Qin, const __nv_bfloat16* __restrict__ KVin,
    const __nv_bfloat16* __restrict__ Wqt, const __nv_bfloat16* __restrict__ Wkt,
    const __nv_bfloat16* __restrict__ Wvt,
    const float* __restrict__ bq, const float* __restrict__ bk,
    const float* __restrict__ bv,
    __nv_bfloat16* __restrict__ Qp, __nv_bfloat16* __restrict__ Kp,
    __nv_bfloat16* __restrict__ Vp, int M, int N, int K)
{
    const __nv_bfloat16 *A, *Wt;
    const float* bias;
    __nv_bfloat16* Cb;
    switch (blockIdx.z) {
        case 0:  A = Qin;  Wt = Wqt; bias = bq; Cb = Qp; break;
        case 1:  A = KVin; Wt = Wkt; bias = bk; Cb = Kp; break;
        default: A = KVin; Wt = Wvt; bias = bv; Cb = Vp; break;
    }
    gemm_body(A, Wt, bias, nullptr, Cb, nullptr, M, N, K);
}

// Output projection + residual (fp32 out).
__global__ __launch_bounds__(256) void gemm_out_kernel(
    const __nv_bfloat16* __restrict__ Ctx, const __nv_bfloat16* __restrict__ Wot,
    const float* __restrict__ bo, const float* __restrict__ residual,
    float* __restrict__ X, int M, int N, int K)
{
    gemm_body(Ctx, Wot, bo, residual, nullptr, X, M, N, K);
}

// ---------------------------------------------------------------------------
// Flash attention, bf16 m16n8k16 with ldmatrix, 3-stage cp.async pipeline.
// 256 threads, 128 q/block. KV tile 64. P stays in registers.
// ---------------------------------------------------------------------------
#define KS_LD 72
#define ATT_STG (64 * KS_LD)
#define ATT_SMEM (2 * NSTG * ATT_STG * 2)      // K+V stages, bytes

__global__ __launch_bounds__(256) void attention_bf16_kernel(
    const __nv_bfloat16* __restrict__ Qp, const __nv_bfloat16* __restrict__ Kp,
    const __nv_bfloat16* __restrict__ Vt, __nv_bfloat16* __restrict__ Ctx)
{
    extern __shared__ __nv_bfloat16 asmem[];
    __nv_bfloat16* KsB  = asmem;                     // [NSTG][ATT_STG]
    __nv_bfloat16* VtsB = asmem + NSTG * ATT_STG;    // [NSTG][ATT_STG]

    const int tid  = threadIdx.x;
    const int lane = tid & 31;
    const int warp = tid >> 5;
    const int r0 = lane >> 2, qd = lane & 3;
    const int b  = blockIdx.z;
    const int h  = blockIdx.y;
    const int q0 = blockIdx.x * 128;
    const int lr = warp * 16 + r0;
    const float SC = 0.125f * 1.44269504089f;

    const int bLOff = ((lane >> 4) * 8 + (lane & 7)) * KS_LD + ((lane >> 3) & 1) * 8;

    const __nv_bfloat16* Kbase  = Kp + ((size_t)b * LKV_ * HID_ + h * HD_);
    const __nv_bfloat16* Vtbase = Vt + ((size_t)(b * NH_ + h) * HD_) * LKV_;

    auto fill = [&](int s, int kt) {
        __nv_bfloat16* Ks  = KsB + s * ATT_STG;
        __nv_bfloat16* Vts = VtsB + s * ATT_STG;
        #pragma unroll
        for (int i = 0; i < 2; i++) {
            int q = tid + 256 * i;
            int r = q >> 3, c = (q & 7) * 8;
            cp_async16(&Ks[r * KS_LD + c], &Kbase[(size_t)(kt + r) * HID_ + c]);
        }
        #pragma unroll
        for (int i = 0; i < 2; i++) {
            int q = tid + 256 * i;
            int d = q >> 3, c = (q & 7) * 8;
            cp_async16(&Vts[d * KS_LD + c], &Vtbase[(size_t)d * LKV_ + kt + c]);
        }
    };

    // Prologue fills overlap with Q fragment loads below
    fill(0, 0);
    cp_commit();
    fill(1, 64);
    cp_commit();

    // Q fragments from GMEM
    uint32_t qf[4][4];
    {
        const __nv_bfloat16* q0p = Qp + ((size_t)(b * LQ_ + q0 + lr) * HID_ + h * HD_);
        const __nv_bfloat16* q1p = q0p + (size_t)8 * HID_;
        #pragma unroll
        for (int ks = 0; ks < 4; ks++) {
            int c = 16 * ks + 2 * qd;
            qf[ks][0] = *(const uint32_t*)&q0p[c];
            qf[ks][1] = *(const uint32_t*)&q1p[c];
            qf[ks][2] = *(const uint32_t*)&q0p[c + 8];
            qf[ks][3] = *(const uint32_t*)&q1p[c + 8];
        }
    }

    float of[8][4];
    #pragma unroll
    for (int nt = 0; nt < 8; nt++)
        #pragma unroll
        for (int i = 0; i < 4; i++) of[nt][i] = 0.f;
    float m0 = -1e30f, m1 = -1e30f, l0 = 0.f, l1 = 0.f;

    const int nT = LKV_ / 64;
    for (int t = 0; t < nT; t++) {
        if (t + NSTG - 1 < nT) fill((t + NSTG - 1) % NSTG, (t + NSTG - 1) * 64);
        cp_commit();
        cp_wait<NSTG - 1>();
        __syncthreads();

        const __nv_bfloat16* Ks  = KsB + (t % NSTG) * ATT_STG + bLOff;
        const __nv_bfloat16* Vts = VtsB + (t % NSTG) * ATT_STG + bLOff;

        // S = Q @ K^T
        float sf[8][4];
        #pragma unroll
        for (int nt = 0; nt < 8; nt++)
            #pragma unroll
            for (int i = 0; i < 4; i++) sf[nt][i] = 0.f;
        #pragma unroll
        for (int ks = 0; ks < 4; ks++) {
            #pragma unroll
            for (int ntp = 0; ntp < 4; ntp++) {
                uint32_t kr[4];
                ldsm_x4(kr, Ks + 16 * ntp * KS_LD + 16 * ks);
                mma_bf16(sf[2 * ntp],     qf[ks], &kr[0]);
                mma_bf16(sf[2 * ntp + 1], qf[ks], &kr[2]);
            }
        }

        // Online softmax in exp2 domain
        float mloc0 = -1e30f, mloc1 = -1e30f;
        #pragma unroll
        for (int nt = 0; nt < 8; nt++) {
            mloc0 = fmaxf(mloc0, fmaxf(sf[nt][0], sf[nt][1]));
            mloc1 = fmaxf(mloc1, fmaxf(sf[nt][2], sf[nt][3]));
        }
        mloc0 = fmaxf(mloc0, __shfl_xor_sync(0xffffffff, mloc0, 1));
        mloc0 = fmaxf(mloc0, __shfl_xor_sync(0xffffffff, mloc0, 2));
        mloc1 = fmaxf(mloc1, __shfl_xor_sync(0xffffffff, mloc1, 1));
        mloc1 = fmaxf(mloc1, __shfl_xor_sync(0xffffffff, mloc1, 2));

        float mn0 = fmaxf(m0, mloc0), mn1 = fmaxf(m1, mloc1);
        float corr0 = exp2_fast((m0 - mn0) * SC);
        float corr1 = exp2_fast((m1 - mn1) * SC);
        m0 = mn0; m1 = mn1;

        float rs0 = 0.f, rs1 = 0.f;
        float pv[8][4];
        #pragma unroll
        for (int nt = 0; nt < 8; nt++) {
            pv[nt][0] = exp2_fast((sf[nt][0] - mn0) * SC);
            pv[nt][1] = exp2_fast((sf[nt][1] - mn0) * SC);
            pv[nt][2] = exp2_fast((sf[nt][2] - mn1) * SC);
            pv[nt][3] = exp2_fast((sf[nt][3] - mn1) * SC);
            rs0 += pv[nt][0] + pv[nt][1];
            rs1 += pv[nt][2] + pv[nt][3];
        }
        rs0 += __shfl_xor_sync(0xffffffff, rs0, 1);
        rs0 += __shfl_xor_sync(0xffffffff, rs0, 2);
        rs1 += __shfl_xor_sync(0xffffffff, rs1, 1);
        rs1 += __shfl_xor_sync(0xffffffff, rs1, 2);
        l0 = l0 * corr0 + rs0;
        l1 = l1 * corr1 + rs1;

        #pragma unroll
        for (int nt = 0; nt < 8; nt++) {
            of[nt][0] *= corr0; of[nt][1] *= corr0;
            of[nt][2] *= corr1; of[nt][3] *= corr1;
        }

        // P A-fragments from registers
        uint32_t pf[4][4];
        #pragma unroll
        for (int ks = 0; ks < 4; ks++) {
            pf[ks][0] = pack_bf16(pv[2 * ks][0],     pv[2 * ks][1]);
            pf[ks][1] = pack_bf16(pv[2 * ks][2],     pv[2 * ks][3]);
            pf[ks][2] = pack_bf16(pv[2 * ks + 1][0], pv[2 * ks + 1][1]);
            pf[ks][3] = pack_bf16(pv[2 * ks + 1][2], pv[2 * ks + 1][3]);
        }

        // O += P @ V
        #pragma unroll
        for (int ks = 0; ks < 4; ks++) {
            #pragma unroll
            for (int ntp = 0; ntp < 4; ntp++) {
                uint32_t vr[4];
                ldsm_x4(vr, Vts + 16 * ntp * KS_LD + 16 * ks);
                mma_bf16(of[2 * ntp],     pf[ks], &vr[0]);
                mma_bf16(of[2 * ntp + 1], pf[ks], &vr[2]);
            }
        }
        __syncthreads();
    }

    // Normalize + store Ctx (bf16)
    float inv0 = 1.f / l0, inv1 = 1.f / l1;
    __nv_bfloat16* o0p = Ctx + ((size_t)(b * LQ_ + q0 + lr) * HID_ + h * HD_);
    __nv_bfloat16* o1p = o0p + (size_t)8 * HID_;
    #pragma unroll
    for (int nt = 0; nt < 8; nt++) {
        int c = 8 * nt + 2 * qd;
        *(uint32_t*)&o0p[c] = pack_bf16(of[nt][0] * inv0, of[nt][1] * inv0);
        *(uint32_t*)&o1p[c] = pack_bf16(of[nt][2] * inv1, of[nt][3] * inv1);
    }
}

// ---------------------------------------------------------------------------
// LayerNorm over rows of 1024. One block (256 threads) per row.
// ---------------------------------------------------------------------------
__global__ __launch_bounds__(256) void layernorm_kernel(
    const float* __restrict__ X, const float* __restrict__ gamma,
    const float* __restrict__ beta, float* __restrict__ out)
{
    __shared__ float red_s[8];
    __shared__ float red_ss[8];

    const int row = blockIdx.x;
    const int tid = threadIdx.x;
    const float* x = X + (size_t)row * DQ_;

    float s = 0.f, ss = 0.f;
    #pragma unroll
    for (int i = tid; i < DQ_; i += 256) {
        float v = x[i];
        s += v;
        ss += v * v;
    }
    #pragma unroll
    for (int off = 16; off > 0; off >>= 1) {
        s  += __shfl_xor_sync(0xffffffff, s, off);
        ss += __shfl_xor_sync(0xffffffff, ss, off);
    }
    if ((tid & 31) == 0) {
        red_s[tid >> 5] = s;
        red_ss[tid >> 5] = ss;
    }
    __syncthreads();
    if (tid < 32) {
        float a = (tid < 8) ? red_s[tid] : 0.f;
        float c = (tid < 8) ? red_ss[tid] : 0.f;
        #pragma unroll
        for (int off = 4; off > 0; off >>= 1) {
            a += __shfl_xor_sync(0xffffffff, a, off);
            c += __shfl_xor_sync(0xffffffff, c, off);
        }
        if (tid == 0) { red_s[0] = a; red_ss[0] = c; }
    }
    __syncthreads();

    const float mu = red_s[0] * (1.f / DQ_);
    const float var = red_ss[0] * (1.f / DQ_) - mu * mu;
    const float rstd = rsqrtf(var + EPS_);

    float* orow = out + (size_t)row * DQ_;
    for (int i = tid; i < DQ_; i += 256) {
        orow[i] = (x[i] - mu) * rstd * gamma[i] + beta[i];
    }
}

// ---------------------------------------------------------------------------
// Launch
// ---------------------------------------------------------------------------
extern "C" void kernel_launch(void* const* d_in, const int* in_sizes, int n_in,
                              void* d_out, int out_size)
{
    const float* query     = (const float*)d_in[0];
    const float* key_value = (const float*)d_in[1];
    const float* Wq = (const float*)d_in[2];
    const float* bq = (const float*)d_in[3];
    const float* Wk = (const float*)d_in[4];
    const float* bk = (const float*)d_in[5];
    const float* Wv = (const float*)d_in[6];
    const float* bv = (const float*)d_in[7];
    const float* Wo = (const float*)d_in[8];
    const float* bo = (const float*)d_in[9];
    const float* ln_gamma = (const float*)d_in[10];
    const float* ln_beta  = (const float*)d_in[11];
    float* out = (float*)d_out;

    __nv_bfloat16 *Qin, *KVin, *Wqt, *Wkt, *Wvt, *Wot, *Qp, *Kp, *Vp, *Vt, *Ctx;
    float* X;
    cudaGetSymbolAddress((void**)&Qin, g_Qin);
    cudaGetSymbolAddress((void**)&KVin, g_KVin);
    cudaGetSymbolAddress((void**)&Wqt, g_Wqt);
    cudaGetSymbolAddress((void**)&Wkt, g_Wkt);
    cudaGetSymbolAddress((void**)&Wvt, g_Wvt);
    cudaGetSymbolAddress((void**)&Wot, g_Wot);
    cudaGetSymbolAddress((void**)&Qp, g_Qp);
    cudaGetSymbolAddress((void**)&Kp, g_Kp);
    cudaGetSymbolAddress((void**)&Vp, g_Vp);
    cudaGetSymbolAddress((void**)&Vt, g_Vt);
    cudaGetSymbolAddress((void**)&Ctx, g_Ctx);
    cudaGetSymbolAddress((void**)&X, g_X);

    const int M = B_ * LQ_;
    const int K = DQ_;
    const int N = HID_;

    cudaFuncSetAttribute(gemm_qkv_kernel,
                         cudaFuncAttributeMaxDynamicSharedMemorySize, GEMM_SMEM);
    cudaFuncSetAttribute(gemm_out_kernel,
                         cudaFuncAttributeMaxDynamicSharedMemorySize, GEMM_SMEM);
    cudaFuncSetAttribute(attention_bf16_kernel,
                         cudaFuncAttributeMaxDynamicSharedMemorySize, ATT_SMEM);

    // Input conversions (consolidated)
    const int n4 = (M * K) / 4;
    dim3 cgrid(n4 / 256, 1, 2);
    cvt_bf16_kernel<<<cgrid, 256>>>(query, Qin, key_value, KVin, n4);
    dim3 wgrid(32, 32, 4);
    cvt_transpose_w_kernel<<<wgrid, 256>>>(Wq, Wqt, Wk, Wkt, Wv, Wvt, Wo, Wot);

    // Fused Q/K/V projections: one launch, 768 blocks
    dim3 qkvgrid(N / GBN, M / GBM, 3);
    gemm_qkv_kernel<<<qkvgrid, 256, GEMM_SMEM>>>(
        Qin, KVin, Wqt, Wkt, Wvt, bq, bk, bv, Qp, Kp, Vp, M, N, K);

    dim3 vgrid(LKV_ / 64, NH_, B_);
    transpose_v_kernel<<<vgrid, 256>>>(Vp, Vt);

    dim3 agrid(LQ_ / 128, NH_, B_);
    attention_bf16_kernel<<<agrid, 256, ATT_SMEM>>>(Qp, Kp, Vt, Ctx);

    dim3 ogrid(N / GBN, M / GBM);
    gemm_out_kernel<<<ogrid, 256, GEMM_SMEM>>>(Ctx, Wot, bo, query, X, M, DQ_, HID_);

    layernorm_kernel<<<M, 256>>>(X, ln_gamma, ln_beta, out);
}